// round 1
// baseline (speedup 1.0000x reference)
#include <cuda_runtime.h>
#include <math.h>

// ---------------------------------------------------------------------------
// Encoder block: x:[4,2048,1024]
//   h = LN1(x); q,k,v = h @ Wq/Wk/Wv (per-head); attn = softmax(qk^T * C^-0.5) v
//   x1 = x + (concat attn) @ Wproj + bproj
//   out = x1 + relu(LN2(x1) @ W1 + b1) @ W2 + b2
// All fp32 SIMT. Scratch in __device__ globals (no allocation allowed).
// ---------------------------------------------------------------------------

#define BT      8192          // B*T
#define CDIM    1024
#define FFDIM   4096
#define NHEAD   16
#define HDIM    64
#define TSEQ    2048

// scratch buffers
__device__ float g_h   [BT * CDIM];     // ln1 output
__device__ float g_q   [BT * CDIM];     // [B,H,T,D]
__device__ float g_k   [BT * CDIM];
__device__ float g_v   [BT * CDIM];
__device__ float g_att [BT * CDIM];     // [B,T,C] concat heads
__device__ float g_x1  [BT * CDIM];     // residual 1
__device__ float g_h2  [BT * CDIM];     // ln2 output
__device__ float g_ff  [BT * FFDIM];    // ffn hidden
__device__ float g_wqkv[CDIM * 3 * CDIM]; // packed [C, 3C] weight

// ---------------------------------------------------------------------------
// Pack (H,C,D) q/k/v weights into a row-major [C, 3C] matrix, col n = which*1024 + h*64 + d
// ---------------------------------------------------------------------------
__global__ void __launch_bounds__(256) pack_qkv_kernel(
    const float* __restrict__ wq, const float* __restrict__ wk,
    const float* __restrict__ wv, float* __restrict__ out)
{
    int idx = blockIdx.x * 256 + threadIdx.x;       // 0 .. 3*1024*1024-1
    int c = idx / 3072;
    int n = idx - c * 3072;
    int which = n >> 10;
    int nn = n & 1023;
    int h = nn >> 6, d = nn & 63;
    const float* w = (which == 0) ? wq : (which == 1 ? wk : wv);
    out[idx] = w[(h * CDIM + c) * HDIM + d];
}

// ---------------------------------------------------------------------------
// LayerNorm over last dim (1024). One block (256 thr) per row, float4 IO.
// ---------------------------------------------------------------------------
__global__ void __launch_bounds__(256) ln_kernel(
    const float* __restrict__ x, const float* __restrict__ gamma,
    const float* __restrict__ beta, float* __restrict__ out)
{
    __shared__ float red[8];
    int row = blockIdx.x;
    const float4* xr = (const float4*)(x + (size_t)row * CDIM);
    float4 v = xr[threadIdx.x];

    float s = v.x + v.y + v.z + v.w;
    #pragma unroll
    for (int o = 16; o > 0; o >>= 1) s += __shfl_xor_sync(0xffffffffu, s, o);
    if ((threadIdx.x & 31) == 0) red[threadIdx.x >> 5] = s;
    __syncthreads();
    float tot = 0.f;
    #pragma unroll
    for (int i = 0; i < 8; i++) tot += red[i];
    float mu = tot * (1.0f / 1024.0f);

    float dx = v.x - mu, dy = v.y - mu, dz = v.z - mu, dw = v.w - mu;
    float sq = dx*dx + dy*dy + dz*dz + dw*dw;
    #pragma unroll
    for (int o = 16; o > 0; o >>= 1) sq += __shfl_xor_sync(0xffffffffu, sq, o);
    __syncthreads();                       // everyone done reading red
    if ((threadIdx.x & 31) == 0) red[threadIdx.x >> 5] = sq;
    __syncthreads();
    float vt = 0.f;
    #pragma unroll
    for (int i = 0; i < 8; i++) vt += red[i];
    float rstd = rsqrtf(vt * (1.0f / 1024.0f) + 1e-5f);

    float4 g4 = ((const float4*)gamma)[threadIdx.x];
    float4 b4 = ((const float4*)beta)[threadIdx.x];
    float4 o4;
    o4.x = dx * rstd * g4.x + b4.x;
    o4.y = dy * rstd * g4.y + b4.y;
    o4.z = dz * rstd * g4.z + b4.z;
    o4.w = dw * rstd * g4.w + b4.w;
    ((float4*)(out + (size_t)row * CDIM))[threadIdx.x] = o4;
}

// ---------------------------------------------------------------------------
// SGEMM 128x128x8, 256 threads, 8x8 micro-tile (strip-mined 2x2 of 4x4 quads).
// EPI: 0=QKV scatter, 1=proj(+bias+residual), 2=relu(+bias), 3=ffn2(+bias+residual)
// All dims are exact multiples of tile sizes (M=8192, N in {1024,3072,4096}, K in {1024,4096}).
// ---------------------------------------------------------------------------
template<int EPI>
__global__ void __launch_bounds__(256) gemm_kernel(
    const float* __restrict__ A, const float* __restrict__ B,
    int M, int N, int K,
    const float* __restrict__ bias, const float* __restrict__ residual,
    float* __restrict__ C0, float* __restrict__ C1, float* __restrict__ C2)
{
    __shared__ float As[8][132];   // [k][m], padded to kill store conflicts
    __shared__ float Bs[8][128];   // [k][n]

    int tid = threadIdx.x;
    int bc = blockIdx.x, br = blockIdx.y;
    int tr = tid >> 4, tc = tid & 15;

    int arow = tid >> 1;            // 0..127
    int acol = (tid & 1) * 4;       // 0 or 4
    int bkrow = tid >> 5;           // 0..7
    int bcol  = (tid & 31) * 4;     // 0..124

    const float* Ap = A + (size_t)(br * 128 + arow) * K + acol;
    const float* Bp = B + (size_t)bkrow * N + bc * 128 + bcol;

    float acc[8][8] = {};

    for (int k0 = 0; k0 < K; k0 += 8) {
        float4 av = *(const float4*)(Ap + k0);
        float4 bv = *(const float4*)(Bp + (size_t)k0 * N);
        __syncthreads();
        As[acol + 0][arow] = av.x;
        As[acol + 1][arow] = av.y;
        As[acol + 2][arow] = av.z;
        As[acol + 3][arow] = av.w;
        *(float4*)&Bs[bkrow][bcol] = bv;
        __syncthreads();

        #pragma unroll
        for (int kk = 0; kk < 8; kk++) {
            float a[8], b[8];
            *(float4*)(a)     = *(const float4*)&As[kk][tr * 4];
            *(float4*)(a + 4) = *(const float4*)&As[kk][64 + tr * 4];
            *(float4*)(b)     = *(const float4*)&Bs[kk][tc * 4];
            *(float4*)(b + 4) = *(const float4*)&Bs[kk][64 + tc * 4];
            #pragma unroll
            for (int i = 0; i < 8; i++)
                #pragma unroll
                for (int j = 0; j < 8; j++)
                    acc[i][j] = fmaf(a[i], b[j], acc[i][j]);
        }
    }

    #pragma unroll
    for (int i = 0; i < 8; i++) {
        int m = br * 128 + ((i < 4) ? (tr * 4 + i) : (64 + tr * 4 + i - 4));
        #pragma unroll
        for (int j = 0; j < 8; j++) {
            int n = bc * 128 + ((j < 4) ? (tc * 4 + j) : (64 + tc * 4 + j - 4));
            float val = acc[i][j];
            if (EPI == 0) {
                // scatter to q/k/v [B,H,T,D]
                int which = n >> 10, nn = n & 1023;
                int h = nn >> 6, d = nn & 63;
                int b = m >> 11, t = m & 2047;
                float* dst = (which == 0) ? C0 : (which == 1 ? C1 : C2);
                dst[(size_t)((b << 4) + h) * (TSEQ * HDIM) + t * HDIM + d] = val;
            } else if (EPI == 1 || EPI == 3) {
                size_t o = (size_t)m * N + n;
                C0[o] = val + bias[n] + residual[o];
            } else { // EPI == 2
                size_t o = (size_t)m * N + n;
                float t2 = val + bias[n];
                C0[o] = t2 > 0.f ? t2 : 0.f;
            }
        }
    }
}

// ---------------------------------------------------------------------------
// Fused attention (flash style). Block = 64 queries of one (b,h); 256 threads.
// smem: Qs[d][i] (64x68), Ks[d][j] (64x68), Vs[j][d] (64x64), Ps[i][j] (64x68)
// Thread (ty,tx) owns S/O rows ty*4..+3, cols tx*4..+3. Online softmax across
// the 16 tx lanes via shfl.
// ---------------------------------------------------------------------------
#define QS_PITCH 68
#define ATTN_SMEM_FLOATS (64*QS_PITCH*3 + 64*64)
#define ATTN_SMEM_BYTES  (ATTN_SMEM_FLOATS * 4)

__global__ void __launch_bounds__(256) attn_kernel(
    const float* __restrict__ Q, const float* __restrict__ K,
    const float* __restrict__ V, float* __restrict__ O)
{
    extern __shared__ float sm[];
    float* Qs = sm;                       // [64][68] (d, i)
    float* Ks = Qs + 64 * QS_PITCH;       // [64][68] (d, j)
    float* Vs = Ks + 64 * QS_PITCH;       // [64][64] (j, d)
    float* Ps = Vs + 64 * 64;             // [64][68] (i, j)

    int tid = threadIdx.x;
    int tx = tid & 15, ty = tid >> 4;
    int bh = blockIdx.y;                  // b*16 + h
    int qt = blockIdx.x;

    const float* Qb = Q + ((size_t)bh * TSEQ + qt * 64) * HDIM;
    const float* Kb = K + (size_t)bh * TSEQ * HDIM;
    const float* Vb = V + (size_t)bh * TSEQ * HDIM;

    const float scale = 0.03125f;         // 1024^-0.5 (NOTE: n_embd, not head_size)

    // load Q tile, transposed + pre-scaled
    {
        int d0 = tx * 4;
        #pragma unroll
        for (int r = 0; r < 4; r++) {
            int i = ty + r * 16;
            float4 qv = *(const float4*)(Qb + (size_t)i * HDIM + d0);
            Qs[(d0 + 0) * QS_PITCH + i] = qv.x * scale;
            Qs[(d0 + 1) * QS_PITCH + i] = qv.y * scale;
            Qs[(d0 + 2) * QS_PITCH + i] = qv.z * scale;
            Qs[(d0 + 3) * QS_PITCH + i] = qv.w * scale;
        }
    }

    float mrow[4], lrow[4], o[4][4];
    #pragma unroll
    for (int r = 0; r < 4; r++) {
        mrow[r] = -1e30f; lrow[r] = 0.f;
        #pragma unroll
        for (int c = 0; c < 4; c++) o[r][c] = 0.f;
    }

    for (int kt = 0; kt < TSEQ / 64; kt++) {
        __syncthreads();   // prior O-accum done reading Vs/Ps; prior S done with Ks
        {
            int d0 = tx * 4;
            #pragma unroll
            for (int r = 0; r < 4; r++) {
                int j = ty + r * 16;
                const float* kp = Kb + (size_t)(kt * 64 + j) * HDIM + d0;
                float4 kv = *(const float4*)kp;
                Ks[(d0 + 0) * QS_PITCH + j] = kv.x;
                Ks[(d0 + 1) * QS_PITCH + j] = kv.y;
                Ks[(d0 + 2) * QS_PITCH + j] = kv.z;
                Ks[(d0 + 3) * QS_PITCH + j] = kv.w;
                float4 vv = *(const float4*)(Vb + (size_t)(kt * 64 + j) * HDIM + d0);
                *(float4*)&Vs[j * 64 + d0] = vv;
            }
        }
        __syncthreads();

        // S = Q K^T  (pre-scaled)
        float s[4][4] = {};
        #pragma unroll 4
        for (int d = 0; d < 64; d++) {
            float4 aq = *(const float4*)&Qs[d * QS_PITCH + ty * 4];
            float4 bk = *(const float4*)&Ks[d * QS_PITCH + tx * 4];
            s[0][0] = fmaf(aq.x, bk.x, s[0][0]); s[0][1] = fmaf(aq.x, bk.y, s[0][1]);
            s[0][2] = fmaf(aq.x, bk.z, s[0][2]); s[0][3] = fmaf(aq.x, bk.w, s[0][3]);
            s[1][0] = fmaf(aq.y, bk.x, s[1][0]); s[1][1] = fmaf(aq.y, bk.y, s[1][1]);
            s[1][2] = fmaf(aq.y, bk.z, s[1][2]); s[1][3] = fmaf(aq.y, bk.w, s[1][3]);
            s[2][0] = fmaf(aq.z, bk.x, s[2][0]); s[2][1] = fmaf(aq.z, bk.y, s[2][1]);
            s[2][2] = fmaf(aq.z, bk.z, s[2][2]); s[2][3] = fmaf(aq.z, bk.w, s[2][3]);
            s[3][0] = fmaf(aq.w, bk.x, s[3][0]); s[3][1] = fmaf(aq.w, bk.y, s[3][1]);
            s[3][2] = fmaf(aq.w, bk.z, s[3][2]); s[3][3] = fmaf(aq.w, bk.w, s[3][3]);
        }

        // online softmax per row (reduce across 16 tx lanes; lane = (ty&1)*16+tx)
        #pragma unroll
        for (int r = 0; r < 4; r++) {
            float mx = fmaxf(fmaxf(s[r][0], s[r][1]), fmaxf(s[r][2], s[r][3]));
            #pragma unroll
            for (int off = 1; off < 16; off <<= 1)
                mx = fmaxf(mx, __shfl_xor_sync(0xffffffffu, mx, off));
            float mnew = fmaxf(mrow[r], mx);
            float corr = __expf(mrow[r] - mnew);
            mrow[r] = mnew;
            float p0 = __expf(s[r][0] - mnew);
            float p1 = __expf(s[r][1] - mnew);
            float p2 = __expf(s[r][2] - mnew);
            float p3 = __expf(s[r][3] - mnew);
            float ps = p0 + p1 + p2 + p3;
            #pragma unroll
            for (int off = 1; off < 16; off <<= 1)
                ps += __shfl_xor_sync(0xffffffffu, ps, off);
            lrow[r] = lrow[r] * corr + ps;
            o[r][0] *= corr; o[r][1] *= corr; o[r][2] *= corr; o[r][3] *= corr;
            *(float4*)&Ps[(ty * 4 + r) * QS_PITCH + tx * 4] = make_float4(p0, p1, p2, p3);
        }
        __syncthreads();

        // O += P V
        #pragma unroll 4
        for (int j = 0; j < 64; j++) {
            float4 vv = *(const float4*)&Vs[j * 64 + tx * 4];
            float a0 = Ps[(ty * 4 + 0) * QS_PITCH + j];
            float a1 = Ps[(ty * 4 + 1) * QS_PITCH + j];
            float a2 = Ps[(ty * 4 + 2) * QS_PITCH + j];
            float a3 = Ps[(ty * 4 + 3) * QS_PITCH + j];
            o[0][0] = fmaf(a0, vv.x, o[0][0]); o[0][1] = fmaf(a0, vv.y, o[0][1]);
            o[0][2] = fmaf(a0, vv.z, o[0][2]); o[0][3] = fmaf(a0, vv.w, o[0][3]);
            o[1][0] = fmaf(a1, vv.x, o[1][0]); o[1][1] = fmaf(a1, vv.y, o[1][1]);
            o[1][2] = fmaf(a1, vv.z, o[1][2]); o[1][3] = fmaf(a1, vv.w, o[1][3]);
            o[2][0] = fmaf(a2, vv.x, o[2][0]); o[2][1] = fmaf(a2, vv.y, o[2][1]);
            o[2][2] = fmaf(a2, vv.z, o[2][2]); o[2][3] = fmaf(a2, vv.w, o[2][3]);
            o[3][0] = fmaf(a3, vv.x, o[3][0]); o[3][1] = fmaf(a3, vv.y, o[3][1]);
            o[3][2] = fmaf(a3, vv.z, o[3][2]); o[3][3] = fmaf(a3, vv.w, o[3][3]);
        }
    }

    // write out (concat heads): att[(b*T + t)*C + h*64 + d]
    int b = bh >> 4, h = bh & 15;
    #pragma unroll
    for (int r = 0; r < 4; r++) {
        float inv = 1.0f / lrow[r];
        int t = qt * 64 + ty * 4 + r;
        float4 res = make_float4(o[r][0] * inv, o[r][1] * inv, o[r][2] * inv, o[r][3] * inv);
        *(float4*)&O[((size_t)(b * TSEQ + t)) * CDIM + h * HDIM + tx * 4] = res;
    }
}

// ---------------------------------------------------------------------------
// Host launcher
// ---------------------------------------------------------------------------
extern "C" void kernel_launch(void* const* d_in, const int* in_sizes, int n_in,
                              void* d_out, int out_size)
{
    const float* x      = (const float*)d_in[0];
    const float* wq     = (const float*)d_in[1];
    const float* wk     = (const float*)d_in[2];
    const float* wv     = (const float*)d_in[3];
    const float* w_proj = (const float*)d_in[4];
    const float* b_proj = (const float*)d_in[5];
    const float* w1     = (const float*)d_in[6];
    const float* b1     = (const float*)d_in[7];
    const float* w2     = (const float*)d_in[8];
    const float* b2     = (const float*)d_in[9];
    const float* g1     = (const float*)d_in[10];
    const float* be1    = (const float*)d_in[11];
    const float* g2     = (const float*)d_in[12];
    const float* be2    = (const float*)d_in[13];
    float* out = (float*)d_out;

    float *ph, *pq, *pk, *pv, *patt, *px1, *ph2, *pff, *pwqkv;
    cudaGetSymbolAddress((void**)&ph,    g_h);
    cudaGetSymbolAddress((void**)&pq,    g_q);
    cudaGetSymbolAddress((void**)&pk,    g_k);
    cudaGetSymbolAddress((void**)&pv,    g_v);
    cudaGetSymbolAddress((void**)&patt,  g_att);
    cudaGetSymbolAddress((void**)&px1,   g_x1);
    cudaGetSymbolAddress((void**)&ph2,   g_h2);
    cudaGetSymbolAddress((void**)&pff,   g_ff);
    cudaGetSymbolAddress((void**)&pwqkv, g_wqkv);

    cudaFuncSetAttribute(attn_kernel,
                         cudaFuncAttributeMaxDynamicSharedMemorySize,
                         ATTN_SMEM_BYTES);

    // 1) pack qkv weights -> [C, 3C]
    pack_qkv_kernel<<<(CDIM * 3 * CDIM) / 256, 256>>>(wq, wk, wv, pwqkv);
    // 2) ln1
    ln_kernel<<<BT, 256>>>(x, g1, be1, ph);
    // 3) qkv gemm, scatter to [B,H,T,D]
    gemm_kernel<0><<<dim3(3 * CDIM / 128, BT / 128), 256>>>(
        ph, pwqkv, BT, 3 * CDIM, CDIM, nullptr, nullptr, pq, pk, pv);
    // 4) fused attention
    attn_kernel<<<dim3(TSEQ / 64, 4 * NHEAD), 256, ATTN_SMEM_BYTES>>>(pq, pk, pv, patt);
    // 5) output projection + bias + residual(x) -> x1
    gemm_kernel<1><<<dim3(CDIM / 128, BT / 128), 256>>>(
        patt, w_proj, BT, CDIM, CDIM, b_proj, x, px1, nullptr, nullptr);
    // 6) ln2
    ln_kernel<<<BT, 256>>>(px1, g2, be2, ph2);
    // 7) ffn1: relu(h2 @ w1 + b1)
    gemm_kernel<2><<<dim3(FFDIM / 128, BT / 128), 256>>>(
        ph2, w1, BT, FFDIM, CDIM, b1, nullptr, pff, nullptr, nullptr);
    // 8) ffn2: ff @ w2 + b2 + x1 -> out
    gemm_kernel<3><<<dim3(CDIM / 128, BT / 128), 256>>>(
        pff, w2, BT, CDIM, FFDIM, b2, px1, out, nullptr, nullptr);
}

// round 2
// speedup vs baseline: 1.6009x; 1.6009x over previous
#include <cuda_runtime.h>
#include <math.h>
#include <stdint.h>

// ---------------------------------------------------------------------------
// Encoder block, fp32 IO. GEMMs on tf32 tensor cores (mma.sync.m16n8k8),
// flash-style fp32 attention, fused LN.
// ---------------------------------------------------------------------------

#define BT      8192          // B*T
#define CDIM    1024
#define FFDIM   4096
#define NHEAD   16
#define HDIM    64
#define TSEQ    2048

// scratch buffers
__device__ float g_h   [BT * CDIM];
__device__ float g_q   [BT * CDIM];
__device__ float g_k   [BT * CDIM];
__device__ float g_v   [BT * CDIM];
__device__ float g_att [BT * CDIM];
__device__ float g_x1  [BT * CDIM];
__device__ float g_h2  [BT * CDIM];
__device__ float g_ff  [BT * FFDIM];
__device__ float g_wqkv[CDIM * 3 * CDIM];

// ---------------------------------------------------------------------------
__global__ void __launch_bounds__(256) pack_qkv_kernel(
    const float* __restrict__ wq, const float* __restrict__ wk,
    const float* __restrict__ wv, float* __restrict__ out)
{
    int idx = blockIdx.x * 256 + threadIdx.x;
    int c = idx / 3072;
    int n = idx - c * 3072;
    int which = n >> 10;
    int nn = n & 1023;
    int h = nn >> 6, d = nn & 63;
    const float* w = (which == 0) ? wq : (which == 1 ? wk : wv);
    out[idx] = w[(h * CDIM + c) * HDIM + d];
}

// ---------------------------------------------------------------------------
__global__ void __launch_bounds__(256) ln_kernel(
    const float* __restrict__ x, const float* __restrict__ gamma,
    const float* __restrict__ beta, float* __restrict__ out)
{
    __shared__ float red[8];
    int row = blockIdx.x;
    const float4* xr = (const float4*)(x + (size_t)row * CDIM);
    float4 v = xr[threadIdx.x];

    float s = v.x + v.y + v.z + v.w;
    #pragma unroll
    for (int o = 16; o > 0; o >>= 1) s += __shfl_xor_sync(0xffffffffu, s, o);
    if ((threadIdx.x & 31) == 0) red[threadIdx.x >> 5] = s;
    __syncthreads();
    float tot = 0.f;
    #pragma unroll
    for (int i = 0; i < 8; i++) tot += red[i];
    float mu = tot * (1.0f / 1024.0f);

    float dx = v.x - mu, dy = v.y - mu, dz = v.z - mu, dw = v.w - mu;
    float sq = dx*dx + dy*dy + dz*dz + dw*dw;
    #pragma unroll
    for (int o = 16; o > 0; o >>= 1) sq += __shfl_xor_sync(0xffffffffu, sq, o);
    __syncthreads();
    if ((threadIdx.x & 31) == 0) red[threadIdx.x >> 5] = sq;
    __syncthreads();
    float vt = 0.f;
    #pragma unroll
    for (int i = 0; i < 8; i++) vt += red[i];
    float rstd = rsqrtf(vt * (1.0f / 1024.0f) + 1e-5f);

    float4 g4 = ((const float4*)gamma)[threadIdx.x];
    float4 b4 = ((const float4*)beta)[threadIdx.x];
    float4 o4;
    o4.x = dx * rstd * g4.x + b4.x;
    o4.y = dy * rstd * g4.y + b4.y;
    o4.z = dz * rstd * g4.z + b4.z;
    o4.w = dw * rstd * g4.w + b4.w;
    ((float4*)(out + (size_t)row * CDIM))[threadIdx.x] = o4;
}

// ---------------------------------------------------------------------------
// TF32 tensor-core GEMM: 128x128 block tile, BK=16, 256 thr = 8 warps (4m x 2n),
// warp tile 32x64 = 2x8 fragments of m16n8k8. Double-buffered smem.
// EPI: 0=QKV scatter, 1=proj(+bias+residual), 2=relu(+bias), 3=ffn2(+bias+residual)
// ---------------------------------------------------------------------------
#define APITCH 20
#define BPITCH 136

__device__ __forceinline__ float to_tf32(float x) {
    uint32_t r;
    asm("cvt.rna.tf32.f32 %0, %1;" : "=r"(r) : "f"(x));
    return __uint_as_float(r);
}

template<int EPI>
__global__ void __launch_bounds__(256) tgemm_kernel(
    const float* __restrict__ A, const float* __restrict__ B,
    int M, int N, int K,
    const float* __restrict__ bias, const float* __restrict__ residual,
    float* __restrict__ C0, float* __restrict__ C1, float* __restrict__ C2)
{
    __shared__ float As[2][128 * APITCH];
    __shared__ float Bs[2][16 * BPITCH];

    const int tid  = threadIdx.x;
    const int bn   = blockIdx.x, bm = blockIdx.y;
    const int warp = tid >> 5, lane = tid & 31;
    const int wm   = warp & 3, wn = warp >> 2;     // 4x2 warp grid
    const int g    = lane >> 2, t = lane & 3;

    // global A load: 2 float4 per thread, same row
    const int a_m = tid >> 1;
    const int a_k = (tid & 1) * 8;
    const float* Ap = A + (size_t)(bm * 128 + a_m) * K + a_k;
    // global B load: 2 float4 per thread (rows b_k and b_k+8)
    const int b_k = tid >> 5;
    const int b_n = (tid & 31) * 4;
    const float* Bp = B + (size_t)b_k * N + bn * 128 + b_n;

    float4 ar0, ar1, br0, br1;

    float c[2][8][4];
    #pragma unroll
    for (int i = 0; i < 2; i++)
        #pragma unroll
        for (int j = 0; j < 8; j++)
            #pragma unroll
            for (int q = 0; q < 4; q++) c[i][j][q] = 0.f;

    auto gload = [&](int kt) {
        const float* ap = Ap + kt * 16;
        ar0 = *(const float4*)ap;
        ar1 = *(const float4*)(ap + 4);
        const float* bp = Bp + (size_t)kt * 16 * N;
        br0 = *(const float4*)bp;
        br1 = *(const float4*)(bp + (size_t)8 * N);
    };
    auto sstore = [&](int buf) {
        float* as = &As[buf][a_m * APITCH + a_k];
        as[0] = to_tf32(ar0.x); as[1] = to_tf32(ar0.y);
        as[2] = to_tf32(ar0.z); as[3] = to_tf32(ar0.w);
        as[4] = to_tf32(ar1.x); as[5] = to_tf32(ar1.y);
        as[6] = to_tf32(ar1.z); as[7] = to_tf32(ar1.w);
        float* bs0 = &Bs[buf][b_k * BPITCH + b_n];
        bs0[0] = to_tf32(br0.x); bs0[1] = to_tf32(br0.y);
        bs0[2] = to_tf32(br0.z); bs0[3] = to_tf32(br0.w);
        float* bs1 = &Bs[buf][(b_k + 8) * BPITCH + b_n];
        bs1[0] = to_tf32(br1.x); bs1[1] = to_tf32(br1.y);
        bs1[2] = to_tf32(br1.z); bs1[3] = to_tf32(br1.w);
    };
    auto compute = [&](int buf) {
        const float* as = As[buf];
        const float* bs = Bs[buf];
        #pragma unroll
        for (int ks = 0; ks < 2; ks++) {
            const int k8 = ks * 8;
            uint32_t a[2][4];
            #pragma unroll
            for (int mi = 0; mi < 2; mi++) {
                int r = wm * 32 + mi * 16 + g;
                a[mi][0] = __float_as_uint(as[(r    ) * APITCH + k8 + t]);
                a[mi][1] = __float_as_uint(as[(r + 8) * APITCH + k8 + t]);
                a[mi][2] = __float_as_uint(as[(r    ) * APITCH + k8 + t + 4]);
                a[mi][3] = __float_as_uint(as[(r + 8) * APITCH + k8 + t + 4]);
            }
            #pragma unroll
            for (int ni = 0; ni < 8; ni++) {
                int cc = wn * 64 + ni * 8 + g;
                uint32_t b0 = __float_as_uint(bs[(k8 + t    ) * BPITCH + cc]);
                uint32_t b1 = __float_as_uint(bs[(k8 + t + 4) * BPITCH + cc]);
                #pragma unroll
                for (int mi = 0; mi < 2; mi++) {
                    asm volatile(
                        "mma.sync.aligned.m16n8k8.row.col.f32.tf32.tf32.f32 "
                        "{%0,%1,%2,%3}, {%4,%5,%6,%7}, {%8,%9}, {%0,%1,%2,%3};"
                        : "+f"(c[mi][ni][0]), "+f"(c[mi][ni][1]),
                          "+f"(c[mi][ni][2]), "+f"(c[mi][ni][3])
                        : "r"(a[mi][0]), "r"(a[mi][1]), "r"(a[mi][2]), "r"(a[mi][3]),
                          "r"(b0), "r"(b1));
                }
            }
        }
    };

    const int nk = K / 16;
    gload(0);
    sstore(0);
    __syncthreads();
    for (int kt = 0; kt < nk; kt++) {
        const int cur = kt & 1;
        if (kt + 1 < nk) gload(kt + 1);
        compute(cur);
        if (kt + 1 < nk) {
            __syncthreads();
            sstore(cur ^ 1);
            __syncthreads();
        }
    }

    // epilogue: thread owns rows (r, r+8), cols (col, col+1) per fragment
    #pragma unroll
    for (int mi = 0; mi < 2; mi++) {
        const int rbase = bm * 128 + wm * 32 + mi * 16 + g;
        #pragma unroll
        for (int ni = 0; ni < 8; ni++) {
            const int col = bn * 128 + wn * 64 + ni * 8 + t * 2;
            #pragma unroll
            for (int half = 0; half < 2; half++) {
                const int m = rbase + half * 8;
                const float v0 = c[mi][ni][half * 2 + 0];
                const float v1 = c[mi][ni][half * 2 + 1];
                if (EPI == 0) {
                    int which = col >> 10, nn = col & 1023;
                    int h = nn >> 6, d = nn & 63;
                    int b = m >> 11, tt = m & 2047;
                    float* dst = (which == 0) ? C0 : (which == 1 ? C1 : C2);
                    *(float2*)&dst[(size_t)((b << 4) + h) * (TSEQ * HDIM)
                                   + tt * HDIM + d] = make_float2(v0, v1);
                } else if (EPI == 1 || EPI == 3) {
                    size_t o = (size_t)m * N + col;
                    float2 r2 = *(const float2*)&residual[o];
                    *(float2*)&C0[o] =
                        make_float2(v0 + bias[col] + r2.x, v1 + bias[col + 1] + r2.y);
                } else { // EPI == 2
                    size_t o = (size_t)m * N + col;
                    float t0 = v0 + bias[col], t1 = v1 + bias[col + 1];
                    *(float2*)&C0[o] =
                        make_float2(t0 > 0.f ? t0 : 0.f, t1 > 0.f ? t1 : 0.f);
                }
            }
        }
    }
}

// ---------------------------------------------------------------------------
// Fused attention (flash style), fp32. Unchanged from round 1.
// ---------------------------------------------------------------------------
#define QS_PITCH 68
#define ATTN_SMEM_FLOATS (64*QS_PITCH*3 + 64*64)
#define ATTN_SMEM_BYTES  (ATTN_SMEM_FLOATS * 4)

__global__ void __launch_bounds__(256) attn_kernel(
    const float* __restrict__ Q, const float* __restrict__ K,
    const float* __restrict__ V, float* __restrict__ O)
{
    extern __shared__ float sm[];
    float* Qs = sm;
    float* Ks = Qs + 64 * QS_PITCH;
    float* Vs = Ks + 64 * QS_PITCH;
    float* Ps = Vs + 64 * 64;

    int tid = threadIdx.x;
    int tx = tid & 15, ty = tid >> 4;
    int bh = blockIdx.y;
    int qt = blockIdx.x;

    const float* Qb = Q + ((size_t)bh * TSEQ + qt * 64) * HDIM;
    const float* Kb = K + (size_t)bh * TSEQ * HDIM;
    const float* Vb = V + (size_t)bh * TSEQ * HDIM;

    const float scale = 0.03125f;   // 1024^-0.5

    {
        int d0 = tx * 4;
        #pragma unroll
        for (int r = 0; r < 4; r++) {
            int i = ty + r * 16;
            float4 qv = *(const float4*)(Qb + (size_t)i * HDIM + d0);
            Qs[(d0 + 0) * QS_PITCH + i] = qv.x * scale;
            Qs[(d0 + 1) * QS_PITCH + i] = qv.y * scale;
            Qs[(d0 + 2) * QS_PITCH + i] = qv.z * scale;
            Qs[(d0 + 3) * QS_PITCH + i] = qv.w * scale;
        }
    }

    float mrow[4], lrow[4], o[4][4];
    #pragma unroll
    for (int r = 0; r < 4; r++) {
        mrow[r] = -1e30f; lrow[r] = 0.f;
        #pragma unroll
        for (int c = 0; c < 4; c++) o[r][c] = 0.f;
    }

    for (int kt = 0; kt < TSEQ / 64; kt++) {
        __syncthreads();
        {
            int d0 = tx * 4;
            #pragma unroll
            for (int r = 0; r < 4; r++) {
                int j = ty + r * 16;
                const float* kp = Kb + (size_t)(kt * 64 + j) * HDIM + d0;
                float4 kv = *(const float4*)kp;
                Ks[(d0 + 0) * QS_PITCH + j] = kv.x;
                Ks[(d0 + 1) * QS_PITCH + j] = kv.y;
                Ks[(d0 + 2) * QS_PITCH + j] = kv.z;
                Ks[(d0 + 3) * QS_PITCH + j] = kv.w;
                float4 vv = *(const float4*)(Vb + (size_t)(kt * 64 + j) * HDIM + d0);
                *(float4*)&Vs[j * 64 + d0] = vv;
            }
        }
        __syncthreads();

        float s[4][4] = {};
        #pragma unroll 4
        for (int d = 0; d < 64; d++) {
            float4 aq = *(const float4*)&Qs[d * QS_PITCH + ty * 4];
            float4 bk = *(const float4*)&Ks[d * QS_PITCH + tx * 4];
            s[0][0] = fmaf(aq.x, bk.x, s[0][0]); s[0][1] = fmaf(aq.x, bk.y, s[0][1]);
            s[0][2] = fmaf(aq.x, bk.z, s[0][2]); s[0][3] = fmaf(aq.x, bk.w, s[0][3]);
            s[1][0] = fmaf(aq.y, bk.x, s[1][0]); s[1][1] = fmaf(aq.y, bk.y, s[1][1]);
            s[1][2] = fmaf(aq.y, bk.z, s[1][2]); s[1][3] = fmaf(aq.y, bk.w, s[1][3]);
            s[2][0] = fmaf(aq.z, bk.x, s[2][0]); s[2][1] = fmaf(aq.z, bk.y, s[2][1]);
            s[2][2] = fmaf(aq.z, bk.z, s[2][2]); s[2][3] = fmaf(aq.z, bk.w, s[2][3]);
            s[3][0] = fmaf(aq.w, bk.x, s[3][0]); s[3][1] = fmaf(aq.w, bk.y, s[3][1]);
            s[3][2] = fmaf(aq.w, bk.z, s[3][2]); s[3][3] = fmaf(aq.w, bk.w, s[3][3]);
        }

        #pragma unroll
        for (int r = 0; r < 4; r++) {
            float mx = fmaxf(fmaxf(s[r][0], s[r][1]), fmaxf(s[r][2], s[r][3]));
            #pragma unroll
            for (int off = 1; off < 16; off <<= 1)
                mx = fmaxf(mx, __shfl_xor_sync(0xffffffffu, mx, off));
            float mnew = fmaxf(mrow[r], mx);
            float corr = __expf(mrow[r] - mnew);
            mrow[r] = mnew;
            float p0 = __expf(s[r][0] - mnew);
            float p1 = __expf(s[r][1] - mnew);
            float p2 = __expf(s[r][2] - mnew);
            float p3 = __expf(s[r][3] - mnew);
            float ps = p0 + p1 + p2 + p3;
            #pragma unroll
            for (int off = 1; off < 16; off <<= 1)
                ps += __shfl_xor_sync(0xffffffffu, ps, off);
            lrow[r] = lrow[r] * corr + ps;
            o[r][0] *= corr; o[r][1] *= corr; o[r][2] *= corr; o[r][3] *= corr;
            *(float4*)&Ps[(ty * 4 + r) * QS_PITCH + tx * 4] = make_float4(p0, p1, p2, p3);
        }
        __syncthreads();

        #pragma unroll 4
        for (int j = 0; j < 64; j++) {
            float4 vv = *(const float4*)&Vs[j * 64 + tx * 4];
            float a0 = Ps[(ty * 4 + 0) * QS_PITCH + j];
            float a1 = Ps[(ty * 4 + 1) * QS_PITCH + j];
            float a2 = Ps[(ty * 4 + 2) * QS_PITCH + j];
            float a3 = Ps[(ty * 4 + 3) * QS_PITCH + j];
            o[0][0] = fmaf(a0, vv.x, o[0][0]); o[0][1] = fmaf(a0, vv.y, o[0][1]);
            o[0][2] = fmaf(a0, vv.z, o[0][2]); o[0][3] = fmaf(a0, vv.w, o[0][3]);
            o[1][0] = fmaf(a1, vv.x, o[1][0]); o[1][1] = fmaf(a1, vv.y, o[1][1]);
            o[1][2] = fmaf(a1, vv.z, o[1][2]); o[1][3] = fmaf(a1, vv.w, o[1][3]);
            o[2][0] = fmaf(a2, vv.x, o[2][0]); o[2][1] = fmaf(a2, vv.y, o[2][1]);
            o[2][2] = fmaf(a2, vv.z, o[2][2]); o[2][3] = fmaf(a2, vv.w, o[2][3]);
            o[3][0] = fmaf(a3, vv.x, o[3][0]); o[3][1] = fmaf(a3, vv.y, o[3][1]);
            o[3][2] = fmaf(a3, vv.z, o[3][2]); o[3][3] = fmaf(a3, vv.w, o[3][3]);
        }
    }

    int b = bh >> 4, h = bh & 15;
    #pragma unroll
    for (int r = 0; r < 4; r++) {
        float inv = 1.0f / lrow[r];
        int t = qt * 64 + ty * 4 + r;
        float4 res = make_float4(o[r][0] * inv, o[r][1] * inv, o[r][2] * inv, o[r][3] * inv);
        *(float4*)&O[((size_t)(b * TSEQ + t)) * CDIM + h * HDIM + tx * 4] = res;
    }
}

// ---------------------------------------------------------------------------
extern "C" void kernel_launch(void* const* d_in, const int* in_sizes, int n_in,
                              void* d_out, int out_size)
{
    const float* x      = (const float*)d_in[0];
    const float* wq     = (const float*)d_in[1];
    const float* wk     = (const float*)d_in[2];
    const float* wv     = (const float*)d_in[3];
    const float* w_proj = (const float*)d_in[4];
    const float* b_proj = (const float*)d_in[5];
    const float* w1     = (const float*)d_in[6];
    const float* b1     = (const float*)d_in[7];
    const float* w2     = (const float*)d_in[8];
    const float* b2     = (const float*)d_in[9];
    const float* g1     = (const float*)d_in[10];
    const float* be1    = (const float*)d_in[11];
    const float* g2     = (const float*)d_in[12];
    const float* be2    = (const float*)d_in[13];
    float* out = (float*)d_out;

    float *ph, *pq, *pk, *pv, *patt, *px1, *ph2, *pff, *pwqkv;
    cudaGetSymbolAddress((void**)&ph,    g_h);
    cudaGetSymbolAddress((void**)&pq,    g_q);
    cudaGetSymbolAddress((void**)&pk,    g_k);
    cudaGetSymbolAddress((void**)&pv,    g_v);
    cudaGetSymbolAddress((void**)&patt,  g_att);
    cudaGetSymbolAddress((void**)&px1,   g_x1);
    cudaGetSymbolAddress((void**)&ph2,   g_h2);
    cudaGetSymbolAddress((void**)&pff,   g_ff);
    cudaGetSymbolAddress((void**)&pwqkv, g_wqkv);

    cudaFuncSetAttribute(attn_kernel,
                         cudaFuncAttributeMaxDynamicSharedMemorySize,
                         ATTN_SMEM_BYTES);

    // 1) pack qkv weights -> [C, 3C]
    pack_qkv_kernel<<<(CDIM * 3 * CDIM) / 256, 256>>>(wq, wk, wv, pwqkv);
    // 2) ln1
    ln_kernel<<<BT, 256>>>(x, g1, be1, ph);
    // 3) qkv gemm (tf32), scatter to [B,H,T,D]
    tgemm_kernel<0><<<dim3(3 * CDIM / 128, BT / 128), 256>>>(
        ph, pwqkv, BT, 3 * CDIM, CDIM, nullptr, nullptr, pq, pk, pv);
    // 4) fused attention
    attn_kernel<<<dim3(TSEQ / 64, 4 * NHEAD), 256, ATTN_SMEM_BYTES>>>(pq, pk, pv, patt);
    // 5) output projection + bias + residual(x) -> x1
    tgemm_kernel<1><<<dim3(CDIM / 128, BT / 128), 256>>>(
        patt, w_proj, BT, CDIM, CDIM, b_proj, x, px1, nullptr, nullptr);
    // 6) ln2
    ln_kernel<<<BT, 256>>>(px1, g2, be2, ph2);
    // 7) ffn1: relu(h2 @ w1 + b1)
    tgemm_kernel<2><<<dim3(FFDIM / 128, BT / 128), 256>>>(
        ph2, w1, BT, FFDIM, CDIM, b1, nullptr, pff, nullptr, nullptr);
    // 8) ffn2: ff @ w2 + b2 + x1 -> out
    tgemm_kernel<3><<<dim3(CDIM / 128, BT / 128), 256>>>(
        pff, w2, BT, CDIM, FFDIM, b2, px1, out, nullptr, nullptr);
}

// round 3
// speedup vs baseline: 2.4731x; 1.5448x over previous
#include <cuda_runtime.h>
#include <math.h>
#include <stdint.h>

// ---------------------------------------------------------------------------
// Encoder block, fp32 IO. GEMMs + attention on tf32 tensor cores.
// ---------------------------------------------------------------------------

#define BT      8192          // B*T
#define CDIM    1024
#define FFDIM   4096
#define NHEAD   16
#define HDIM    64
#define TSEQ    2048

// scratch buffers
__device__ float g_h   [BT * CDIM];
__device__ float g_q   [BT * CDIM];
__device__ float g_k   [BT * CDIM];
__device__ float g_v   [BT * CDIM];
__device__ float g_att [BT * CDIM];
__device__ float g_x1  [BT * CDIM];
__device__ float g_h2  [BT * CDIM];
__device__ float g_ff  [BT * FFDIM];
__device__ float g_wqkv[CDIM * 3 * CDIM];

__device__ __forceinline__ float to_tf32(float x) {
    uint32_t r;
    asm("cvt.rna.tf32.f32 %0, %1;" : "=r"(r) : "f"(x));
    return __uint_as_float(r);
}

// ---------------------------------------------------------------------------
__global__ void __launch_bounds__(256) pack_qkv_kernel(
    const float* __restrict__ wq, const float* __restrict__ wk,
    const float* __restrict__ wv, float* __restrict__ out)
{
    int idx = blockIdx.x * 256 + threadIdx.x;
    int c = idx / 3072;
    int n = idx - c * 3072;
    int which = n >> 10;
    int nn = n & 1023;
    int h = nn >> 6, d = nn & 63;
    const float* w = (which == 0) ? wq : (which == 1 ? wk : wv);
    out[idx] = w[(h * CDIM + c) * HDIM + d];
}

// ---------------------------------------------------------------------------
__global__ void __launch_bounds__(256) ln_kernel(
    const float* __restrict__ x, const float* __restrict__ gamma,
    const float* __restrict__ beta, float* __restrict__ out)
{
    __shared__ float red[8];
    int row = blockIdx.x;
    const float4* xr = (const float4*)(x + (size_t)row * CDIM);
    float4 v = xr[threadIdx.x];

    float s = v.x + v.y + v.z + v.w;
    #pragma unroll
    for (int o = 16; o > 0; o >>= 1) s += __shfl_xor_sync(0xffffffffu, s, o);
    if ((threadIdx.x & 31) == 0) red[threadIdx.x >> 5] = s;
    __syncthreads();
    float tot = 0.f;
    #pragma unroll
    for (int i = 0; i < 8; i++) tot += red[i];
    float mu = tot * (1.0f / 1024.0f);

    float dx = v.x - mu, dy = v.y - mu, dz = v.z - mu, dw = v.w - mu;
    float sq = dx*dx + dy*dy + dz*dz + dw*dw;
    #pragma unroll
    for (int o = 16; o > 0; o >>= 1) sq += __shfl_xor_sync(0xffffffffu, sq, o);
    __syncthreads();
    if ((threadIdx.x & 31) == 0) red[threadIdx.x >> 5] = sq;
    __syncthreads();
    float vt = 0.f;
    #pragma unroll
    for (int i = 0; i < 8; i++) vt += red[i];
    float rstd = rsqrtf(vt * (1.0f / 1024.0f) + 1e-5f);

    float4 g4 = ((const float4*)gamma)[threadIdx.x];
    float4 b4 = ((const float4*)beta)[threadIdx.x];
    float4 o4;
    o4.x = dx * rstd * g4.x + b4.x;
    o4.y = dy * rstd * g4.y + b4.y;
    o4.z = dz * rstd * g4.z + b4.z;
    o4.w = dw * rstd * g4.w + b4.w;
    ((float4*)(out + (size_t)row * CDIM))[threadIdx.x] = o4;
}

// ---------------------------------------------------------------------------
// TF32 tensor-core GEMM (unchanged from round 2).
// ---------------------------------------------------------------------------
#define APITCH 20
#define BPITCH 136

template<int EPI>
__global__ void __launch_bounds__(256) tgemm_kernel(
    const float* __restrict__ A, const float* __restrict__ B,
    int M, int N, int K,
    const float* __restrict__ bias, const float* __restrict__ residual,
    float* __restrict__ C0, float* __restrict__ C1, float* __restrict__ C2)
{
    __shared__ float As[2][128 * APITCH];
    __shared__ float Bs[2][16 * BPITCH];

    const int tid  = threadIdx.x;
    const int bn   = blockIdx.x, bm = blockIdx.y;
    const int warp = tid >> 5, lane = tid & 31;
    const int wm   = warp & 3, wn = warp >> 2;
    const int g    = lane >> 2, t = lane & 3;

    const int a_m = tid >> 1;
    const int a_k = (tid & 1) * 8;
    const float* Ap = A + (size_t)(bm * 128 + a_m) * K + a_k;
    const int b_k = tid >> 5;
    const int b_n = (tid & 31) * 4;
    const float* Bp = B + (size_t)b_k * N + bn * 128 + b_n;

    float4 ar0, ar1, br0, br1;

    float c[2][8][4];
    #pragma unroll
    for (int i = 0; i < 2; i++)
        #pragma unroll
        for (int j = 0; j < 8; j++)
            #pragma unroll
            for (int q = 0; q < 4; q++) c[i][j][q] = 0.f;

    auto gload = [&](int kt) {
        const float* ap = Ap + kt * 16;
        ar0 = *(const float4*)ap;
        ar1 = *(const float4*)(ap + 4);
        const float* bp = Bp + (size_t)kt * 16 * N;
        br0 = *(const float4*)bp;
        br1 = *(const float4*)(bp + (size_t)8 * N);
    };
    auto sstore = [&](int buf) {
        float* as = &As[buf][a_m * APITCH + a_k];
        as[0] = to_tf32(ar0.x); as[1] = to_tf32(ar0.y);
        as[2] = to_tf32(ar0.z); as[3] = to_tf32(ar0.w);
        as[4] = to_tf32(ar1.x); as[5] = to_tf32(ar1.y);
        as[6] = to_tf32(ar1.z); as[7] = to_tf32(ar1.w);
        float* bs0 = &Bs[buf][b_k * BPITCH + b_n];
        bs0[0] = to_tf32(br0.x); bs0[1] = to_tf32(br0.y);
        bs0[2] = to_tf32(br0.z); bs0[3] = to_tf32(br0.w);
        float* bs1 = &Bs[buf][(b_k + 8) * BPITCH + b_n];
        bs1[0] = to_tf32(br1.x); bs1[1] = to_tf32(br1.y);
        bs1[2] = to_tf32(br1.z); bs1[3] = to_tf32(br1.w);
    };
    auto compute = [&](int buf) {
        const float* as = As[buf];
        const float* bs = Bs[buf];
        #pragma unroll
        for (int ks = 0; ks < 2; ks++) {
            const int k8 = ks * 8;
            uint32_t a[2][4];
            #pragma unroll
            for (int mi = 0; mi < 2; mi++) {
                int r = wm * 32 + mi * 16 + g;
                a[mi][0] = __float_as_uint(as[(r    ) * APITCH + k8 + t]);
                a[mi][1] = __float_as_uint(as[(r + 8) * APITCH + k8 + t]);
                a[mi][2] = __float_as_uint(as[(r    ) * APITCH + k8 + t + 4]);
                a[mi][3] = __float_as_uint(as[(r + 8) * APITCH + k8 + t + 4]);
            }
            #pragma unroll
            for (int ni = 0; ni < 8; ni++) {
                int cc = wn * 64 + ni * 8 + g;
                uint32_t b0 = __float_as_uint(bs[(k8 + t    ) * BPITCH + cc]);
                uint32_t b1 = __float_as_uint(bs[(k8 + t + 4) * BPITCH + cc]);
                #pragma unroll
                for (int mi = 0; mi < 2; mi++) {
                    asm volatile(
                        "mma.sync.aligned.m16n8k8.row.col.f32.tf32.tf32.f32 "
                        "{%0,%1,%2,%3}, {%4,%5,%6,%7}, {%8,%9}, {%0,%1,%2,%3};"
                        : "+f"(c[mi][ni][0]), "+f"(c[mi][ni][1]),
                          "+f"(c[mi][ni][2]), "+f"(c[mi][ni][3])
                        : "r"(a[mi][0]), "r"(a[mi][1]), "r"(a[mi][2]), "r"(a[mi][3]),
                          "r"(b0), "r"(b1));
                }
            }
        }
    };

    const int nk = K / 16;
    gload(0);
    sstore(0);
    __syncthreads();
    for (int kt = 0; kt < nk; kt++) {
        const int cur = kt & 1;
        if (kt + 1 < nk) gload(kt + 1);
        compute(cur);
        if (kt + 1 < nk) {
            __syncthreads();
            sstore(cur ^ 1);
            __syncthreads();
        }
    }

    #pragma unroll
    for (int mi = 0; mi < 2; mi++) {
        const int rbase = bm * 128 + wm * 32 + mi * 16 + g;
        #pragma unroll
        for (int ni = 0; ni < 8; ni++) {
            const int col = bn * 128 + wn * 64 + ni * 8 + t * 2;
            #pragma unroll
            for (int half = 0; half < 2; half++) {
                const int m = rbase + half * 8;
                const float v0 = c[mi][ni][half * 2 + 0];
                const float v1 = c[mi][ni][half * 2 + 1];
                if (EPI == 0) {
                    int which = col >> 10, nn = col & 1023;
                    int h = nn >> 6, d = nn & 63;
                    int b = m >> 11, tt = m & 2047;
                    float* dst = (which == 0) ? C0 : (which == 1 ? C1 : C2);
                    *(float2*)&dst[(size_t)((b << 4) + h) * (TSEQ * HDIM)
                                   + tt * HDIM + d] = make_float2(v0, v1);
                } else if (EPI == 1 || EPI == 3) {
                    size_t o = (size_t)m * N + col;
                    float2 r2 = *(const float2*)&residual[o];
                    *(float2*)&C0[o] =
                        make_float2(v0 + bias[col] + r2.x, v1 + bias[col + 1] + r2.y);
                } else {
                    size_t o = (size_t)m * N + col;
                    float t0 = v0 + bias[col], t1 = v1 + bias[col + 1];
                    *(float2*)&C0[o] =
                        make_float2(t0 > 0.f ? t0 : 0.f, t1 > 0.f ? t1 : 0.f);
                }
            }
        }
    }
}

// ---------------------------------------------------------------------------
// Flash attention on tf32 mma. Block = 256 queries of one (b,h); 8 warps,
// warp tile 32 rows. 64-key iterations. P staged per-warp through smem (tf32).
// smem pitches: Q/P/K pitch 68 (bank = 4g+t, conflict-free), V pitch 72
// (bank = 8t+g, conflict-free).
// ---------------------------------------------------------------------------
#define BLKQ 256
#define QP   68
#define KP   68
#define VP   72
#define ATTN_SMEM_BYTES ((BLKQ*QP*2 + 64*KP + 64*VP) * 4)

__global__ void __launch_bounds__(256, 1) attn_kernel(
    const float* __restrict__ Q, const float* __restrict__ K,
    const float* __restrict__ V, float* __restrict__ O)
{
    extern __shared__ float sm[];
    float* Qs = sm;                    // [256][68]
    float* Ps = Qs + BLKQ * QP;        // [256][68]
    float* Ks = Ps + BLKQ * QP;        // [64][68]
    float* Vs = Ks + 64 * KP;          // [64][72]

    const int tid  = threadIdx.x;
    const int w    = tid >> 5, lane = tid & 31;
    const int g    = lane >> 2, t = lane & 3;
    const int bh   = blockIdx.y;
    const int qt   = blockIdx.x;

    const float* Qb = Q + ((size_t)bh * TSEQ + qt * BLKQ) * HDIM;
    const float* Kb = K + (size_t)bh * TSEQ * HDIM;
    const float* Vb = V + (size_t)bh * TSEQ * HDIM;

    const float scale = 0.03125f;      // 1024^-0.5 (n_embd scaling)

    // load Q tile (scaled, tf32), coalesced float4
    #pragma unroll
    for (int q = 0; q < 16; q++) {
        int f  = tid + 256 * q;        // 0..4095 float4s
        int j  = f >> 4;
        int d4 = (f & 15) * 4;
        float4 v = *(const float4*)(Qb + (size_t)j * HDIM + d4);
        float* dst = &Qs[j * QP + d4];
        dst[0] = to_tf32(v.x * scale); dst[1] = to_tf32(v.y * scale);
        dst[2] = to_tf32(v.z * scale); dst[3] = to_tf32(v.w * scale);
    }

    float m_[2][2], l_[2][2];
    float co[2][8][4];
    #pragma unroll
    for (int mi = 0; mi < 2; mi++)
        #pragma unroll
        for (int r = 0; r < 2; r++) { m_[mi][r] = -1e30f; l_[mi][r] = 0.f; }
    #pragma unroll
    for (int mi = 0; mi < 2; mi++)
        #pragma unroll
        for (int ni = 0; ni < 8; ni++)
            #pragma unroll
            for (int q = 0; q < 4; q++) co[mi][ni][q] = 0.f;

    const int rowb = w * 32;           // warp's row base within tile

    for (int kt = 0; kt < TSEQ / 64; kt++) {
        __syncthreads();               // previous iter done with Ks/Vs
        // load K,V tile (tf32), coalesced
        #pragma unroll
        for (int q = 0; q < 4; q++) {
            int f  = tid + 256 * q;    // 0..1023 float4s
            int j  = f >> 4;
            int d4 = (f & 15) * 4;
            const float* kp = Kb + (size_t)(kt * 64 + j) * HDIM + d4;
            float4 kv = *(const float4*)kp;
            float* kd = &Ks[j * KP + d4];
            kd[0] = to_tf32(kv.x); kd[1] = to_tf32(kv.y);
            kd[2] = to_tf32(kv.z); kd[3] = to_tf32(kv.w);
            float4 vv = *(const float4*)(Vb + (size_t)(kt * 64 + j) * HDIM + d4);
            float* vd = &Vs[j * VP + d4];
            vd[0] = to_tf32(vv.x); vd[1] = to_tf32(vv.y);
            vd[2] = to_tf32(vv.z); vd[3] = to_tf32(vv.w);
        }
        __syncthreads();

        // S = Q K^T : warp computes 32 rows x 64 keys
        float cs[2][8][4];
        #pragma unroll
        for (int mi = 0; mi < 2; mi++)
            #pragma unroll
            for (int ni = 0; ni < 8; ni++)
                #pragma unroll
                for (int q = 0; q < 4; q++) cs[mi][ni][q] = 0.f;

        #pragma unroll
        for (int k8 = 0; k8 < 64; k8 += 8) {
            uint32_t a[2][4];
            #pragma unroll
            for (int mi = 0; mi < 2; mi++) {
                int r = rowb + mi * 16 + g;
                a[mi][0] = __float_as_uint(Qs[(r    ) * QP + k8 + t]);
                a[mi][1] = __float_as_uint(Qs[(r + 8) * QP + k8 + t]);
                a[mi][2] = __float_as_uint(Qs[(r    ) * QP + k8 + t + 4]);
                a[mi][3] = __float_as_uint(Qs[(r + 8) * QP + k8 + t + 4]);
            }
            #pragma unroll
            for (int ni = 0; ni < 8; ni++) {
                uint32_t b0 = __float_as_uint(Ks[(ni * 8 + g) * KP + k8 + t]);
                uint32_t b1 = __float_as_uint(Ks[(ni * 8 + g) * KP + k8 + t + 4]);
                #pragma unroll
                for (int mi = 0; mi < 2; mi++) {
                    asm volatile(
                        "mma.sync.aligned.m16n8k8.row.col.f32.tf32.tf32.f32 "
                        "{%0,%1,%2,%3}, {%4,%5,%6,%7}, {%8,%9}, {%0,%1,%2,%3};"
                        : "+f"(cs[mi][ni][0]), "+f"(cs[mi][ni][1]),
                          "+f"(cs[mi][ni][2]), "+f"(cs[mi][ni][3])
                        : "r"(a[mi][0]), "r"(a[mi][1]), "r"(a[mi][2]), "r"(a[mi][3]),
                          "r"(b0), "r"(b1));
                }
            }
        }

        // online softmax; rows per thread: (mi,r) -> rowb + mi*16 + g + 8r
        #pragma unroll
        for (int mi = 0; mi < 2; mi++) {
            #pragma unroll
            for (int r = 0; r < 2; r++) {
                float mx = -1e30f;
                #pragma unroll
                for (int ni = 0; ni < 8; ni++)
                    mx = fmaxf(mx, fmaxf(cs[mi][ni][2*r], cs[mi][ni][2*r+1]));
                mx = fmaxf(mx, __shfl_xor_sync(0xffffffffu, mx, 1));
                mx = fmaxf(mx, __shfl_xor_sync(0xffffffffu, mx, 2));
                float mnew = fmaxf(m_[mi][r], mx);
                float corr = __expf(m_[mi][r] - mnew);
                m_[mi][r] = mnew;
                float rs = 0.f;
                #pragma unroll
                for (int ni = 0; ni < 8; ni++) {
                    float p0 = __expf(cs[mi][ni][2*r]   - mnew);
                    float p1 = __expf(cs[mi][ni][2*r+1] - mnew);
                    rs += p0 + p1;
                    cs[mi][ni][2*r]   = p0;
                    cs[mi][ni][2*r+1] = p1;
                }
                rs += __shfl_xor_sync(0xffffffffu, rs, 1);
                rs += __shfl_xor_sync(0xffffffffu, rs, 2);
                l_[mi][r] = l_[mi][r] * corr + rs;
                #pragma unroll
                for (int ni = 0; ni < 8; ni++) {
                    co[mi][ni][2*r]   *= corr;
                    co[mi][ni][2*r+1] *= corr;
                }
                // stage P row to smem (tf32); only this warp reads it back
                int row = rowb + mi * 16 + g + 8 * r;
                #pragma unroll
                for (int ni = 0; ni < 8; ni++) {
                    *(float2*)&Ps[row * QP + ni * 8 + 2 * t] =
                        make_float2(to_tf32(cs[mi][ni][2*r]),
                                    to_tf32(cs[mi][ni][2*r+1]));
                }
            }
        }
        __syncwarp();

        // O += P V : K-dim = 64 keys
        #pragma unroll
        for (int k8 = 0; k8 < 64; k8 += 8) {
            uint32_t a[2][4];
            #pragma unroll
            for (int mi = 0; mi < 2; mi++) {
                int r = rowb + mi * 16 + g;
                a[mi][0] = __float_as_uint(Ps[(r    ) * QP + k8 + t]);
                a[mi][1] = __float_as_uint(Ps[(r + 8) * QP + k8 + t]);
                a[mi][2] = __float_as_uint(Ps[(r    ) * QP + k8 + t + 4]);
                a[mi][3] = __float_as_uint(Ps[(r + 8) * QP + k8 + t + 4]);
            }
            #pragma unroll
            for (int ni = 0; ni < 8; ni++) {
                uint32_t b0 = __float_as_uint(Vs[(k8 + t    ) * VP + ni * 8 + g]);
                uint32_t b1 = __float_as_uint(Vs[(k8 + t + 4) * VP + ni * 8 + g]);
                #pragma unroll
                for (int mi = 0; mi < 2; mi++) {
                    asm volatile(
                        "mma.sync.aligned.m16n8k8.row.col.f32.tf32.tf32.f32 "
                        "{%0,%1,%2,%3}, {%4,%5,%6,%7}, {%8,%9}, {%0,%1,%2,%3};"
                        : "+f"(co[mi][ni][0]), "+f"(co[mi][ni][1]),
                          "+f"(co[mi][ni][2]), "+f"(co[mi][ni][3])
                        : "r"(a[mi][0]), "r"(a[mi][1]), "r"(a[mi][2]), "r"(a[mi][3]),
                          "r"(b0), "r"(b1));
                }
            }
        }
    }

    // write O: att[(b*T + row)*C + h*64 + d]
    const int b = bh >> 4, h = bh & 15;
    #pragma unroll
    for (int mi = 0; mi < 2; mi++) {
        #pragma unroll
        for (int r = 0; r < 2; r++) {
            float inv = 1.0f / l_[mi][r];
            int row = qt * BLKQ + rowb + mi * 16 + g + 8 * r;
            #pragma unroll
            for (int ni = 0; ni < 8; ni++) {
                int d = ni * 8 + 2 * t;
                *(float2*)&O[((size_t)(b * TSEQ + row)) * CDIM + h * HDIM + d] =
                    make_float2(co[mi][ni][2*r] * inv, co[mi][ni][2*r+1] * inv);
            }
        }
    }
}

// ---------------------------------------------------------------------------
extern "C" void kernel_launch(void* const* d_in, const int* in_sizes, int n_in,
                              void* d_out, int out_size)
{
    const float* x      = (const float*)d_in[0];
    const float* wq     = (const float*)d_in[1];
    const float* wk     = (const float*)d_in[2];
    const float* wv     = (const float*)d_in[3];
    const float* w_proj = (const float*)d_in[4];
    const float* b_proj = (const float*)d_in[5];
    const float* w1     = (const float*)d_in[6];
    const float* b1     = (const float*)d_in[7];
    const float* w2     = (const float*)d_in[8];
    const float* b2     = (const float*)d_in[9];
    const float* g1     = (const float*)d_in[10];
    const float* be1    = (const float*)d_in[11];
    const float* g2     = (const float*)d_in[12];
    const float* be2    = (const float*)d_in[13];
    float* out = (float*)d_out;

    float *ph, *pq, *pk, *pv, *patt, *px1, *ph2, *pff, *pwqkv;
    cudaGetSymbolAddress((void**)&ph,    g_h);
    cudaGetSymbolAddress((void**)&pq,    g_q);
    cudaGetSymbolAddress((void**)&pk,    g_k);
    cudaGetSymbolAddress((void**)&pv,    g_v);
    cudaGetSymbolAddress((void**)&patt,  g_att);
    cudaGetSymbolAddress((void**)&px1,   g_x1);
    cudaGetSymbolAddress((void**)&ph2,   g_h2);
    cudaGetSymbolAddress((void**)&pff,   g_ff);
    cudaGetSymbolAddress((void**)&pwqkv, g_wqkv);

    cudaFuncSetAttribute(attn_kernel,
                         cudaFuncAttributeMaxDynamicSharedMemorySize,
                         ATTN_SMEM_BYTES);

    // 1) pack qkv weights -> [C, 3C]
    pack_qkv_kernel<<<(CDIM * 3 * CDIM) / 256, 256>>>(wq, wk, wv, pwqkv);
    // 2) ln1
    ln_kernel<<<BT, 256>>>(x, g1, be1, ph);
    // 3) qkv gemm (tf32), scatter to [B,H,T,D]
    tgemm_kernel<0><<<dim3(3 * CDIM / 128, BT / 128), 256>>>(
        ph, pwqkv, BT, 3 * CDIM, CDIM, nullptr, nullptr, pq, pk, pv);
    // 4) fused attention (tf32 mma)
    attn_kernel<<<dim3(TSEQ / BLKQ, 4 * NHEAD), 256, ATTN_SMEM_BYTES>>>(
        pq, pk, pv, patt);
    // 5) output projection + bias + residual(x) -> x1
    tgemm_kernel<1><<<dim3(CDIM / 128, BT / 128), 256>>>(
        patt, w_proj, BT, CDIM, CDIM, b_proj, x, px1, nullptr, nullptr);
    // 6) ln2
    ln_kernel<<<BT, 256>>>(px1, g2, be2, ph2);
    // 7) ffn1: relu(h2 @ w1 + b1)
    tgemm_kernel<2><<<dim3(FFDIM / 128, BT / 128), 256>>>(
        ph2, w1, BT, FFDIM, CDIM, b1, nullptr, pff, nullptr, nullptr);
    // 8) ffn2: ff @ w2 + b2 + x1 -> out
    tgemm_kernel<3><<<dim3(CDIM / 128, BT / 128), 256>>>(
        pff, w2, BT, CDIM, FFDIM, b2, px1, out, nullptr, nullptr);
}

// round 4
// speedup vs baseline: 2.6524x; 1.0725x over previous
#include <cuda_runtime.h>
#include <math.h>
#include <stdint.h>

// ---------------------------------------------------------------------------
// Encoder block, fp32 IO. GEMMs + attention on tf32 tensor cores.
// GEMM: 4-stage cp.async pipeline, 128x128x16 tiles, 8 warps.
// ---------------------------------------------------------------------------

#define BT      8192          // B*T
#define CDIM    1024
#define FFDIM   4096
#define NHEAD   16
#define HDIM    64
#define TSEQ    2048

// scratch buffers
__device__ float g_h   [BT * CDIM];
__device__ float g_q   [BT * CDIM];
__device__ float g_k   [BT * CDIM];
__device__ float g_v   [BT * CDIM];
__device__ float g_att [BT * CDIM];
__device__ float g_x1  [BT * CDIM];
__device__ float g_h2  [BT * CDIM];
__device__ float g_ff  [BT * FFDIM];
__device__ float g_wqkv[CDIM * 3 * CDIM];

__device__ __forceinline__ float to_tf32(float x) {
    uint32_t r;
    asm("cvt.rna.tf32.f32 %0, %1;" : "=r"(r) : "f"(x));
    return __uint_as_float(r);
}
__device__ __forceinline__ uint32_t ld_tf32(const float* p) {
    uint32_t r;
    asm("cvt.rna.tf32.f32 %0, %1;" : "=r"(r) : "f"(*p));
    return r;
}
__device__ __forceinline__ void cp16(void* smem, const void* gmem) {
    uint32_t s = (uint32_t)__cvta_generic_to_shared(smem);
    asm volatile("cp.async.ca.shared.global [%0], [%1], 16;\n" :: "r"(s), "l"(gmem));
}
__device__ __forceinline__ void cp_commit() {
    asm volatile("cp.async.commit_group;\n" ::: "memory");
}
template<int N>
__device__ __forceinline__ void cp_wait() {
    asm volatile("cp.async.wait_group %0;\n" :: "n"(N) : "memory");
}

// ---------------------------------------------------------------------------
__global__ void __launch_bounds__(256) pack_qkv_kernel(
    const float* __restrict__ wq, const float* __restrict__ wk,
    const float* __restrict__ wv, float* __restrict__ out)
{
    int idx = blockIdx.x * 256 + threadIdx.x;
    int c = idx / 3072;
    int n = idx - c * 3072;
    int which = n >> 10;
    int nn = n & 1023;
    int h = nn >> 6, d = nn & 63;
    const float* w = (which == 0) ? wq : (which == 1 ? wk : wv);
    out[idx] = w[(h * CDIM + c) * HDIM + d];
}

// ---------------------------------------------------------------------------
__global__ void __launch_bounds__(256) ln_kernel(
    const float* __restrict__ x, const float* __restrict__ gamma,
    const float* __restrict__ beta, float* __restrict__ out)
{
    __shared__ float red[8];
    int row = blockIdx.x;
    const float4* xr = (const float4*)(x + (size_t)row * CDIM);
    float4 v = xr[threadIdx.x];

    float s = v.x + v.y + v.z + v.w;
    #pragma unroll
    for (int o = 16; o > 0; o >>= 1) s += __shfl_xor_sync(0xffffffffu, s, o);
    if ((threadIdx.x & 31) == 0) red[threadIdx.x >> 5] = s;
    __syncthreads();
    float tot = 0.f;
    #pragma unroll
    for (int i = 0; i < 8; i++) tot += red[i];
    float mu = tot * (1.0f / 1024.0f);

    float dx = v.x - mu, dy = v.y - mu, dz = v.z - mu, dw = v.w - mu;
    float sq = dx*dx + dy*dy + dz*dz + dw*dw;
    #pragma unroll
    for (int o = 16; o > 0; o >>= 1) sq += __shfl_xor_sync(0xffffffffu, sq, o);
    __syncthreads();
    if ((threadIdx.x & 31) == 0) red[threadIdx.x >> 5] = sq;
    __syncthreads();
    float vt = 0.f;
    #pragma unroll
    for (int i = 0; i < 8; i++) vt += red[i];
    float rstd = rsqrtf(vt * (1.0f / 1024.0f) + 1e-5f);

    float4 g4 = ((const float4*)gamma)[threadIdx.x];
    float4 b4 = ((const float4*)beta)[threadIdx.x];
    float4 o4;
    o4.x = dx * rstd * g4.x + b4.x;
    o4.y = dy * rstd * g4.y + b4.y;
    o4.z = dz * rstd * g4.z + b4.z;
    o4.w = dw * rstd * g4.w + b4.w;
    ((float4*)(out + (size_t)row * CDIM))[threadIdx.x] = o4;
}

// ---------------------------------------------------------------------------
// TF32 tensor-core GEMM, 4-stage cp.async pipeline.
// Tile 128x128x16, 8 warps (4m x 2n), warp tile 32x64 of m16n8k8 fragments.
// EPI: 0=QKV scatter, 1=proj(+bias+residual), 2=relu(+bias), 3=ffn2(+bias+residual)
// ---------------------------------------------------------------------------
#define APITCH 20
#define BPITCH 136
#define GSTAGES 4
#define ASTG (128 * APITCH)
#define BSTG (16 * BPITCH)
#define GEMM_SMEM_BYTES (GSTAGES * (ASTG + BSTG) * 4)

template<int EPI>
__global__ void __launch_bounds__(256, 2) tgemm_kernel(
    const float* __restrict__ A, const float* __restrict__ B,
    int M, int N, int K,
    const float* __restrict__ bias, const float* __restrict__ residual,
    float* __restrict__ C0, float* __restrict__ C1, float* __restrict__ C2)
{
    extern __shared__ float dsm[];
    float* As = dsm;                       // GSTAGES x 128 x APITCH
    float* Bs = dsm + GSTAGES * ASTG;      // GSTAGES x 16 x BPITCH

    const int tid  = threadIdx.x;
    const int bn   = blockIdx.x, bm = blockIdx.y;
    const int warp = tid >> 5, lane = tid & 31;
    const int wm   = warp & 3, wn = warp >> 2;
    const int g    = lane >> 2, t = lane & 3;

    // A copy: thread -> row tid/2, cols (tid&1)*8 .. +7 (two 16B chunks)
    const float* Ap = A + (size_t)(bm * 128 + (tid >> 1)) * K + (tid & 1) * 8;
    float* Asw = As + (tid >> 1) * APITCH + (tid & 1) * 8;
    // B copy: thread -> rows tid/32 and tid/32+8, col (tid&31)*4 (16B each)
    const float* Bp = B + (size_t)(tid >> 5) * N + bn * 128 + (tid & 31) * 4;
    float* Bsw = Bs + (tid >> 5) * BPITCH + (tid & 31) * 4;

    float c[2][8][4];
    #pragma unroll
    for (int i = 0; i < 2; i++)
        #pragma unroll
        for (int j = 0; j < 8; j++)
            #pragma unroll
            for (int q = 0; q < 4; q++) c[i][j][q] = 0.f;

    const int nk = K / 16;

    auto issue = [&](int kt) {
        const int st = kt & (GSTAGES - 1);
        const float* ag = Ap + kt * 16;
        float* ad = Asw + st * ASTG;
        cp16(ad, ag);
        cp16(ad + 4, ag + 4);
        const float* bg = Bp + (size_t)kt * 16 * N;
        float* bd = Bsw + st * BSTG;
        cp16(bd, bg);
        cp16(bd + 8 * BPITCH, bg + (size_t)8 * N);
    };

    // prologue: fill stages 0..2
    #pragma unroll
    for (int s = 0; s < GSTAGES - 1; s++) { issue(s); cp_commit(); }

    for (int kt = 0; kt < nk; kt++) {
        cp_wait<GSTAGES - 2>();
        __syncthreads();
        if (kt + GSTAGES - 1 < nk) issue(kt + GSTAGES - 1);
        cp_commit();

        const int buf = kt & (GSTAGES - 1);
        const float* as = As + buf * ASTG;
        const float* bs = Bs + buf * BSTG;
        #pragma unroll
        for (int ks = 0; ks < 2; ks++) {
            const int k8 = ks * 8;
            uint32_t a[2][4];
            #pragma unroll
            for (int mi = 0; mi < 2; mi++) {
                int r = wm * 32 + mi * 16 + g;
                a[mi][0] = ld_tf32(&as[(r    ) * APITCH + k8 + t]);
                a[mi][1] = ld_tf32(&as[(r + 8) * APITCH + k8 + t]);
                a[mi][2] = ld_tf32(&as[(r    ) * APITCH + k8 + t + 4]);
                a[mi][3] = ld_tf32(&as[(r + 8) * APITCH + k8 + t + 4]);
            }
            #pragma unroll
            for (int ni = 0; ni < 8; ni++) {
                int cc = wn * 64 + ni * 8 + g;
                uint32_t b0 = ld_tf32(&bs[(k8 + t    ) * BPITCH + cc]);
                uint32_t b1 = ld_tf32(&bs[(k8 + t + 4) * BPITCH + cc]);
                #pragma unroll
                for (int mi = 0; mi < 2; mi++) {
                    asm volatile(
                        "mma.sync.aligned.m16n8k8.row.col.f32.tf32.tf32.f32 "
                        "{%0,%1,%2,%3}, {%4,%5,%6,%7}, {%8,%9}, {%0,%1,%2,%3};"
                        : "+f"(c[mi][ni][0]), "+f"(c[mi][ni][1]),
                          "+f"(c[mi][ni][2]), "+f"(c[mi][ni][3])
                        : "r"(a[mi][0]), "r"(a[mi][1]), "r"(a[mi][2]), "r"(a[mi][3]),
                          "r"(b0), "r"(b1));
                }
            }
        }
    }

    // epilogue
    #pragma unroll
    for (int mi = 0; mi < 2; mi++) {
        const int rbase = bm * 128 + wm * 32 + mi * 16 + g;
        #pragma unroll
        for (int ni = 0; ni < 8; ni++) {
            const int col = bn * 128 + wn * 64 + ni * 8 + t * 2;
            #pragma unroll
            for (int half = 0; half < 2; half++) {
                const int m = rbase + half * 8;
                const float v0 = c[mi][ni][half * 2 + 0];
                const float v1 = c[mi][ni][half * 2 + 1];
                if (EPI == 0) {
                    int which = col >> 10, nn = col & 1023;
                    int h = nn >> 6, d = nn & 63;
                    int b = m >> 11, tt = m & 2047;
                    float* dst = (which == 0) ? C0 : (which == 1 ? C1 : C2);
                    *(float2*)&dst[(size_t)((b << 4) + h) * (TSEQ * HDIM)
                                   + tt * HDIM + d] = make_float2(v0, v1);
                } else if (EPI == 1 || EPI == 3) {
                    size_t o = (size_t)m * N + col;
                    float2 r2 = *(const float2*)&residual[o];
                    *(float2*)&C0[o] =
                        make_float2(v0 + bias[col] + r2.x, v1 + bias[col + 1] + r2.y);
                } else {
                    size_t o = (size_t)m * N + col;
                    float t0 = v0 + bias[col], t1 = v1 + bias[col + 1];
                    *(float2*)&C0[o] =
                        make_float2(t0 > 0.f ? t0 : 0.f, t1 > 0.f ? t1 : 0.f);
                }
            }
        }
    }
}

// ---------------------------------------------------------------------------
// Flash attention on tf32 mma (unchanged from round 3).
// ---------------------------------------------------------------------------
#define BLKQ 256
#define QP   68
#define KP   68
#define VP   72
#define ATTN_SMEM_BYTES ((BLKQ*QP*2 + 64*KP + 64*VP) * 4)

__global__ void __launch_bounds__(256, 1) attn_kernel(
    const float* __restrict__ Q, const float* __restrict__ K,
    const float* __restrict__ V, float* __restrict__ O)
{
    extern __shared__ float sm[];
    float* Qs = sm;                    // [256][68]
    float* Ps = Qs + BLKQ * QP;        // [256][68]
    float* Ks = Ps + BLKQ * QP;        // [64][68]
    float* Vs = Ks + 64 * KP;          // [64][72]

    const int tid  = threadIdx.x;
    const int w    = tid >> 5, lane = tid & 31;
    const int g    = lane >> 2, t = lane & 3;
    const int bh   = blockIdx.y;
    const int qt   = blockIdx.x;

    const float* Qb = Q + ((size_t)bh * TSEQ + qt * BLKQ) * HDIM;
    const float* Kb = K + (size_t)bh * TSEQ * HDIM;
    const float* Vb = V + (size_t)bh * TSEQ * HDIM;

    const float scale = 0.03125f;      // 1024^-0.5

    #pragma unroll
    for (int q = 0; q < 16; q++) {
        int f  = tid + 256 * q;
        int j  = f >> 4;
        int d4 = (f & 15) * 4;
        float4 v = *(const float4*)(Qb + (size_t)j * HDIM + d4);
        float* dst = &Qs[j * QP + d4];
        dst[0] = to_tf32(v.x * scale); dst[1] = to_tf32(v.y * scale);
        dst[2] = to_tf32(v.z * scale); dst[3] = to_tf32(v.w * scale);
    }

    float m_[2][2], l_[2][2];
    float co[2][8][4];
    #pragma unroll
    for (int mi = 0; mi < 2; mi++)
        #pragma unroll
        for (int r = 0; r < 2; r++) { m_[mi][r] = -1e30f; l_[mi][r] = 0.f; }
    #pragma unroll
    for (int mi = 0; mi < 2; mi++)
        #pragma unroll
        for (int ni = 0; ni < 8; ni++)
            #pragma unroll
            for (int q = 0; q < 4; q++) co[mi][ni][q] = 0.f;

    const int rowb = w * 32;

    for (int kt = 0; kt < TSEQ / 64; kt++) {
        __syncthreads();
        #pragma unroll
        for (int q = 0; q < 4; q++) {
            int f  = tid + 256 * q;
            int j  = f >> 4;
            int d4 = (f & 15) * 4;
            const float* kp = Kb + (size_t)(kt * 64 + j) * HDIM + d4;
            float4 kv = *(const float4*)kp;
            float* kd = &Ks[j * KP + d4];
            kd[0] = to_tf32(kv.x); kd[1] = to_tf32(kv.y);
            kd[2] = to_tf32(kv.z); kd[3] = to_tf32(kv.w);
            float4 vv = *(const float4*)(Vb + (size_t)(kt * 64 + j) * HDIM + d4);
            float* vd = &Vs[j * VP + d4];
            vd[0] = to_tf32(vv.x); vd[1] = to_tf32(vv.y);
            vd[2] = to_tf32(vv.z); vd[3] = to_tf32(vv.w);
        }
        __syncthreads();

        float cs[2][8][4];
        #pragma unroll
        for (int mi = 0; mi < 2; mi++)
            #pragma unroll
            for (int ni = 0; ni < 8; ni++)
                #pragma unroll
                for (int q = 0; q < 4; q++) cs[mi][ni][q] = 0.f;

        #pragma unroll
        for (int k8 = 0; k8 < 64; k8 += 8) {
            uint32_t a[2][4];
            #pragma unroll
            for (int mi = 0; mi < 2; mi++) {
                int r = rowb + mi * 16 + g;
                a[mi][0] = __float_as_uint(Qs[(r    ) * QP + k8 + t]);
                a[mi][1] = __float_as_uint(Qs[(r + 8) * QP + k8 + t]);
                a[mi][2] = __float_as_uint(Qs[(r    ) * QP + k8 + t + 4]);
                a[mi][3] = __float_as_uint(Qs[(r + 8) * QP + k8 + t + 4]);
            }
            #pragma unroll
            for (int ni = 0; ni < 8; ni++) {
                uint32_t b0 = __float_as_uint(Ks[(ni * 8 + g) * KP + k8 + t]);
                uint32_t b1 = __float_as_uint(Ks[(ni * 8 + g) * KP + k8 + t + 4]);
                #pragma unroll
                for (int mi = 0; mi < 2; mi++) {
                    asm volatile(
                        "mma.sync.aligned.m16n8k8.row.col.f32.tf32.tf32.f32 "
                        "{%0,%1,%2,%3}, {%4,%5,%6,%7}, {%8,%9}, {%0,%1,%2,%3};"
                        : "+f"(cs[mi][ni][0]), "+f"(cs[mi][ni][1]),
                          "+f"(cs[mi][ni][2]), "+f"(cs[mi][ni][3])
                        : "r"(a[mi][0]), "r"(a[mi][1]), "r"(a[mi][2]), "r"(a[mi][3]),
                          "r"(b0), "r"(b1));
                }
            }
        }

        #pragma unroll
        for (int mi = 0; mi < 2; mi++) {
            #pragma unroll
            for (int r = 0; r < 2; r++) {
                float mx = -1e30f;
                #pragma unroll
                for (int ni = 0; ni < 8; ni++)
                    mx = fmaxf(mx, fmaxf(cs[mi][ni][2*r], cs[mi][ni][2*r+1]));
                mx = fmaxf(mx, __shfl_xor_sync(0xffffffffu, mx, 1));
                mx = fmaxf(mx, __shfl_xor_sync(0xffffffffu, mx, 2));
                float mnew = fmaxf(m_[mi][r], mx);
                float corr = __expf(m_[mi][r] - mnew);
                m_[mi][r] = mnew;
                float rs = 0.f;
                #pragma unroll
                for (int ni = 0; ni < 8; ni++) {
                    float p0 = __expf(cs[mi][ni][2*r]   - mnew);
                    float p1 = __expf(cs[mi][ni][2*r+1] - mnew);
                    rs += p0 + p1;
                    cs[mi][ni][2*r]   = p0;
                    cs[mi][ni][2*r+1] = p1;
                }
                rs += __shfl_xor_sync(0xffffffffu, rs, 1);
                rs += __shfl_xor_sync(0xffffffffu, rs, 2);
                l_[mi][r] = l_[mi][r] * corr + rs;
                #pragma unroll
                for (int ni = 0; ni < 8; ni++) {
                    co[mi][ni][2*r]   *= corr;
                    co[mi][ni][2*r+1] *= corr;
                }
                int row = rowb + mi * 16 + g + 8 * r;
                #pragma unroll
                for (int ni = 0; ni < 8; ni++) {
                    *(float2*)&Ps[row * QP + ni * 8 + 2 * t] =
                        make_float2(to_tf32(cs[mi][ni][2*r]),
                                    to_tf32(cs[mi][ni][2*r+1]));
                }
            }
        }
        __syncwarp();

        #pragma unroll
        for (int k8 = 0; k8 < 64; k8 += 8) {
            uint32_t a[2][4];
            #pragma unroll
            for (int mi = 0; mi < 2; mi++) {
                int r = rowb + mi * 16 + g;
                a[mi][0] = __float_as_uint(Ps[(r    ) * QP + k8 + t]);
                a[mi][1] = __float_as_uint(Ps[(r + 8) * QP + k8 + t]);
                a[mi][2] = __float_as_uint(Ps[(r    ) * QP + k8 + t + 4]);
                a[mi][3] = __float_as_uint(Ps[(r + 8) * QP + k8 + t + 4]);
            }
            #pragma unroll
            for (int ni = 0; ni < 8; ni++) {
                uint32_t b0 = __float_as_uint(Vs[(k8 + t    ) * VP + ni * 8 + g]);
                uint32_t b1 = __float_as_uint(Vs[(k8 + t + 4) * VP + ni * 8 + g]);
                #pragma unroll
                for (int mi = 0; mi < 2; mi++) {
                    asm volatile(
                        "mma.sync.aligned.m16n8k8.row.col.f32.tf32.tf32.f32 "
                        "{%0,%1,%2,%3}, {%4,%5,%6,%7}, {%8,%9}, {%0,%1,%2,%3};"
                        : "+f"(co[mi][ni][0]), "+f"(co[mi][ni][1]),
                          "+f"(co[mi][ni][2]), "+f"(co[mi][ni][3])
                        : "r"(a[mi][0]), "r"(a[mi][1]), "r"(a[mi][2]), "r"(a[mi][3]),
                          "r"(b0), "r"(b1));
                }
            }
        }
    }

    const int b = bh >> 4, h = bh & 15;
    #pragma unroll
    for (int mi = 0; mi < 2; mi++) {
        #pragma unroll
        for (int r = 0; r < 2; r++) {
            float inv = 1.0f / l_[mi][r];
            int row = qt * BLKQ + rowb + mi * 16 + g + 8 * r;
            #pragma unroll
            for (int ni = 0; ni < 8; ni++) {
                int d = ni * 8 + 2 * t;
                *(float2*)&O[((size_t)(b * TSEQ + row)) * CDIM + h * HDIM + d] =
                    make_float2(co[mi][ni][2*r] * inv, co[mi][ni][2*r+1] * inv);
            }
        }
    }
}

// ---------------------------------------------------------------------------
extern "C" void kernel_launch(void* const* d_in, const int* in_sizes, int n_in,
                              void* d_out, int out_size)
{
    const float* x      = (const float*)d_in[0];
    const float* wq     = (const float*)d_in[1];
    const float* wk     = (const float*)d_in[2];
    const float* wv     = (const float*)d_in[3];
    const float* w_proj = (const float*)d_in[4];
    const float* b_proj = (const float*)d_in[5];
    const float* w1     = (const float*)d_in[6];
    const float* b1     = (const float*)d_in[7];
    const float* w2     = (const float*)d_in[8];
    const float* b2     = (const float*)d_in[9];
    const float* g1     = (const float*)d_in[10];
    const float* be1    = (const float*)d_in[11];
    const float* g2     = (const float*)d_in[12];
    const float* be2    = (const float*)d_in[13];
    float* out = (float*)d_out;

    float *ph, *pq, *pk, *pv, *patt, *px1, *ph2, *pff, *pwqkv;
    cudaGetSymbolAddress((void**)&ph,    g_h);
    cudaGetSymbolAddress((void**)&pq,    g_q);
    cudaGetSymbolAddress((void**)&pk,    g_k);
    cudaGetSymbolAddress((void**)&pv,    g_v);
    cudaGetSymbolAddress((void**)&patt,  g_att);
    cudaGetSymbolAddress((void**)&px1,   g_x1);
    cudaGetSymbolAddress((void**)&ph2,   g_h2);
    cudaGetSymbolAddress((void**)&pff,   g_ff);
    cudaGetSymbolAddress((void**)&pwqkv, g_wqkv);

    cudaFuncSetAttribute(attn_kernel,
                         cudaFuncAttributeMaxDynamicSharedMemorySize,
                         ATTN_SMEM_BYTES);
    cudaFuncSetAttribute(tgemm_kernel<0>,
                         cudaFuncAttributeMaxDynamicSharedMemorySize, GEMM_SMEM_BYTES);
    cudaFuncSetAttribute(tgemm_kernel<1>,
                         cudaFuncAttributeMaxDynamicSharedMemorySize, GEMM_SMEM_BYTES);
    cudaFuncSetAttribute(tgemm_kernel<2>,
                         cudaFuncAttributeMaxDynamicSharedMemorySize, GEMM_SMEM_BYTES);
    cudaFuncSetAttribute(tgemm_kernel<3>,
                         cudaFuncAttributeMaxDynamicSharedMemorySize, GEMM_SMEM_BYTES);

    // 1) pack qkv weights -> [C, 3C]
    pack_qkv_kernel<<<(CDIM * 3 * CDIM) / 256, 256>>>(wq, wk, wv, pwqkv);
    // 2) ln1
    ln_kernel<<<BT, 256>>>(x, g1, be1, ph);
    // 3) qkv gemm (tf32), scatter to [B,H,T,D]
    tgemm_kernel<0><<<dim3(3 * CDIM / 128, BT / 128), 256, GEMM_SMEM_BYTES>>>(
        ph, pwqkv, BT, 3 * CDIM, CDIM, nullptr, nullptr, pq, pk, pv);
    // 4) fused attention (tf32 mma)
    attn_kernel<<<dim3(TSEQ / BLKQ, 4 * NHEAD), 256, ATTN_SMEM_BYTES>>>(
        pq, pk, pv, patt);
    // 5) output projection + bias + residual(x) -> x1
    tgemm_kernel<1><<<dim3(CDIM / 128, BT / 128), 256, GEMM_SMEM_BYTES>>>(
        patt, w_proj, BT, CDIM, CDIM, b_proj, x, px1, nullptr, nullptr);
    // 6) ln2
    ln_kernel<<<BT, 256>>>(px1, g2, be2, ph2);
    // 7) ffn1: relu(h2 @ w1 + b1)
    tgemm_kernel<2><<<dim3(FFDIM / 128, BT / 128), 256, GEMM_SMEM_BYTES>>>(
        ph2, w1, BT, FFDIM, CDIM, b1, nullptr, pff, nullptr, nullptr);
    // 8) ffn2: ff @ w2 + b2 + x1 -> out
    tgemm_kernel<3><<<dim3(CDIM / 128, BT / 128), 256, GEMM_SMEM_BYTES>>>(
        pff, w2, BT, FFDIM ? CDIM : CDIM, FFDIM, b2, px1, out, nullptr, nullptr);
}

// round 6
// speedup vs baseline: 4.8921x; 1.8444x over previous
#include <cuda_runtime.h>
#include <cuda_fp16.h>
#include <math.h>
#include <stdint.h>

// ---------------------------------------------------------------------------
// Encoder block, fp32 IO. All tensor math on fp16 mma.sync.m16n8k16 (fp32 acc).
// ---------------------------------------------------------------------------

#define BT      8192
#define CDIM    1024
#define FFDIM   4096
#define NHEAD   16
#define HDIM    64
#define TSEQ    2048

// scratch
__device__ __half g_q   [BT * CDIM];   // [B,H,T,D] fp16 (pre-scaled by C^-0.5)
__device__ __half g_k   [BT * CDIM];
__device__ __half g_v   [BT * CDIM];
__device__ float  g_x1  [BT * CDIM];
__device__ __half g_h   [BT * CDIM];
__device__ __half g_h2  [BT * CDIM];
__device__ __half g_att [BT * CDIM];
__device__ __half g_ff  [BT * FFDIM];
__device__ __half g_wqkvT [3 * CDIM * CDIM];   // [3072][1024] (n,k)
__device__ __half g_wprojT[CDIM * CDIM];
__device__ __half g_w1T   [FFDIM * CDIM];
__device__ __half g_w2T   [CDIM * FFDIM];

// ---------------------------------------------------------------------------
__device__ __forceinline__ void cp16(uint32_t smem, const void* gmem) {
    asm volatile("cp.async.cg.shared.global [%0], [%1], 16;" :: "r"(smem), "l"(gmem));
}
__device__ __forceinline__ void cp_commit() {
    asm volatile("cp.async.commit_group;" ::: "memory");
}
template<int N>
__device__ __forceinline__ void cp_wait() {
    asm volatile("cp.async.wait_group %0;" :: "n"(N) : "memory");
}
__device__ __forceinline__ uint32_t smem_u32(const void* p) {
    uint32_t a;
    asm("{ .reg .u64 t; cvta.to.shared.u64 t, %1; cvt.u32.u64 %0, t; }"
        : "=r"(a) : "l"(p));
    return a;
}
__device__ __forceinline__ void mma_f16(
    float& c0, float& c1, float& c2, float& c3,
    uint32_t a0, uint32_t a1, uint32_t a2, uint32_t a3,
    uint32_t b0, uint32_t b1)
{
    asm volatile(
        "mma.sync.aligned.m16n8k16.row.col.f32.f16.f16.f32 "
        "{%0,%1,%2,%3}, {%4,%5,%6,%7}, {%8,%9}, {%0,%1,%2,%3};"
        : "+f"(c0), "+f"(c1), "+f"(c2), "+f"(c3)
        : "r"(a0), "r"(a1), "r"(a2), "r"(a3), "r"(b0), "r"(b1));
}
__device__ __forceinline__ void ldmx2t(uint32_t& r0, uint32_t& r1, uint32_t addr) {
    asm volatile("ldmatrix.sync.aligned.m8n8.x2.trans.shared.b16 {%0,%1}, [%2];"
                 : "=r"(r0), "=r"(r1) : "r"(addr));
}

// ---------------------------------------------------------------------------
// Weight prep: fp32 [K][N] -> fp16 [N][K]
// ---------------------------------------------------------------------------
__global__ void __launch_bounds__(256) transpose_to_half(
    const float* __restrict__ src, __half* __restrict__ dst, int K, int N)
{
    __shared__ float tile[32][33];
    int n0 = blockIdx.x * 32, k0 = blockIdx.y * 32;
    int tx = threadIdx.x & 31, ty = threadIdx.x >> 5;
    #pragma unroll
    for (int r = ty; r < 32; r += 8)
        tile[r][tx] = src[(size_t)(k0 + r) * N + n0 + tx];
    __syncthreads();
    #pragma unroll
    for (int r = ty; r < 32; r += 8)
        dst[(size_t)(n0 + r) * K + k0 + tx] = __float2half(tile[tx][r]);
}

__global__ void __launch_bounds__(256) pack_qkv_t(
    const float* __restrict__ wq, const float* __restrict__ wk,
    const float* __restrict__ wv, __half* __restrict__ dst)
{
    __shared__ float tile[32][33];
    int wh = blockIdx.z;
    int which = wh >> 4, h = wh & 15;
    const float* w = (which == 0) ? wq : (which == 1 ? wk : wv);
    int c0 = blockIdx.x * 32, d0 = blockIdx.y * 32;
    int tx = threadIdx.x & 31, ty = threadIdx.x >> 5;
    #pragma unroll
    for (int r = ty; r < 32; r += 8)
        tile[r][tx] = w[(size_t)(h * CDIM + c0 + r) * HDIM + d0 + tx];
    __syncthreads();
    #pragma unroll
    for (int r = ty; r < 32; r += 8)
        dst[(size_t)(which * 1024 + h * 64 + d0 + r) * CDIM + c0 + tx] =
            __float2half(tile[tx][r]);
}

// ---------------------------------------------------------------------------
// LayerNorm: fp32 in -> fp16 out
// ---------------------------------------------------------------------------
__global__ void __launch_bounds__(256) ln_kernel(
    const float* __restrict__ x, const float* __restrict__ gamma,
    const float* __restrict__ beta, __half* __restrict__ out)
{
    __shared__ float red[8];
    int row = blockIdx.x;
    const float4* xr = (const float4*)(x + (size_t)row * CDIM);
    float4 v = xr[threadIdx.x];

    float s = v.x + v.y + v.z + v.w;
    #pragma unroll
    for (int o = 16; o > 0; o >>= 1) s += __shfl_xor_sync(0xffffffffu, s, o);
    if ((threadIdx.x & 31) == 0) red[threadIdx.x >> 5] = s;
    __syncthreads();
    float tot = 0.f;
    #pragma unroll
    for (int i = 0; i < 8; i++) tot += red[i];
    float mu = tot * (1.0f / 1024.0f);

    float dx = v.x - mu, dy = v.y - mu, dz = v.z - mu, dw = v.w - mu;
    float sq = dx*dx + dy*dy + dz*dz + dw*dw;
    #pragma unroll
    for (int o = 16; o > 0; o >>= 1) sq += __shfl_xor_sync(0xffffffffu, sq, o);
    __syncthreads();
    if ((threadIdx.x & 31) == 0) red[threadIdx.x >> 5] = sq;
    __syncthreads();
    float vt = 0.f;
    #pragma unroll
    for (int i = 0; i < 8; i++) vt += red[i];
    float rstd = rsqrtf(vt * (1.0f / 1024.0f) + 1e-5f);

    float4 g4 = ((const float4*)gamma)[threadIdx.x];
    float4 b4 = ((const float4*)beta)[threadIdx.x];
    __half2* orow = (__half2*)(out + (size_t)row * CDIM);
    orow[threadIdx.x * 2 + 0] =
        __floats2half2_rn(dx * rstd * g4.x + b4.x, dy * rstd * g4.y + b4.y);
    orow[threadIdx.x * 2 + 1] =
        __floats2half2_rn(dz * rstd * g4.z + b4.z, dw * rstd * g4.w + b4.w);
}

// ---------------------------------------------------------------------------
// fp16 tensor-core GEMM, 4-stage cp.async: D[M,N] = A[M,K] * B[N,K]^T.
// Tile 128x128xBK32, 8 warps (4m x 2n). smem pitch 40 halfs (conflict-free).
// EPI: 0 = QKV scatter -> fp16 q(scaled)/k/v
//      1 = proj + bias + residual -> fp32
//      2 = relu + bias -> fp16
//      3 = ffn2 + bias + residual -> fp32
// ---------------------------------------------------------------------------
#define HP 40
#define HSTG (128 * HP)                 // halfs per A (or B) stage tile
#define HSTAGES 4
#define HGEMM_SMEM (HSTAGES * 2 * HSTG * 2)   // bytes = 81920

template<int EPI>
__global__ void __launch_bounds__(256, 2) hgemm_kernel(
    const __half* __restrict__ A, const __half* __restrict__ B,
    int M, int N, int K,
    const float* __restrict__ bias, const float* __restrict__ residual,
    float* __restrict__ Cf,
    __half* __restrict__ H0, __half* __restrict__ H1, __half* __restrict__ H2)
{
    extern __shared__ __half hsm[];
    const uint32_t sbase = smem_u32(hsm);

    const int tid  = threadIdx.x;
    const int bn   = blockIdx.x, bm = blockIdx.y;
    const int warp = tid >> 5, lane = tid & 31;
    const int wm   = warp & 3, wn = warp >> 2;
    const int g    = lane >> 2, t = lane & 3;

    // copy mapping: row = tid/2, 32B chunk pair at (tid&1)*16 halfs
    const int crow = tid >> 1;
    const int ccol = (tid & 1) * 16;     // halfs
    const __half* Ag = A + (size_t)(bm * 128 + crow) * K + ccol;
    const __half* Bg = B + (size_t)(bn * 128 + crow) * K + ccol;
    const uint32_t sA = sbase + (crow * HP + ccol) * 2;            // bytes
    const uint32_t sB = sbase + (HSTAGES * HSTG + crow * HP + ccol) * 2;

    float c[2][8][4];
    #pragma unroll
    for (int i = 0; i < 2; i++)
        #pragma unroll
        for (int j = 0; j < 8; j++)
            #pragma unroll
            for (int q = 0; q < 4; q++) c[i][j][q] = 0.f;

    const int nk = K >> 5;               // K/32

    auto issue = [&](int kt) {
        const uint32_t st = (uint32_t)(kt & (HSTAGES - 1)) * HSTG * 2;  // bytes
        const __half* ag = Ag + (size_t)kt * 32;
        const __half* bg = Bg + (size_t)kt * 32;
        cp16(sA + st, ag);
        cp16(sA + st + 16, ag + 8);
        cp16(sB + st, bg);
        cp16(sB + st + 16, bg + 8);
    };

    #pragma unroll
    for (int s = 0; s < HSTAGES - 1; s++) { issue(s); cp_commit(); }

    const __half* AsAll = hsm;
    const __half* BsAll = hsm + HSTAGES * HSTG;

    for (int kt = 0; kt < nk; kt++) {
        cp_wait<HSTAGES - 2>();
        __syncthreads();
        if (kt + HSTAGES - 1 < nk) issue(kt + HSTAGES - 1);
        cp_commit();

        const __half* as = AsAll + (kt & (HSTAGES - 1)) * HSTG;
        const __half* bs = BsAll + (kt & (HSTAGES - 1)) * HSTG;
        #pragma unroll
        for (int ks = 0; ks < 2; ks++) {
            const int k16 = ks * 16;
            uint32_t a[2][4];
            #pragma unroll
            for (int mi = 0; mi < 2; mi++) {
                const int r = wm * 32 + mi * 16 + g;
                a[mi][0] = *(const uint32_t*)&as[(r    ) * HP + k16 + 2 * t];
                a[mi][1] = *(const uint32_t*)&as[(r + 8) * HP + k16 + 2 * t];
                a[mi][2] = *(const uint32_t*)&as[(r    ) * HP + k16 + 2 * t + 8];
                a[mi][3] = *(const uint32_t*)&as[(r + 8) * HP + k16 + 2 * t + 8];
            }
            #pragma unroll
            for (int ni = 0; ni < 8; ni++) {
                const int nr = wn * 64 + ni * 8 + g;
                uint32_t b0 = *(const uint32_t*)&bs[nr * HP + k16 + 2 * t];
                uint32_t b1 = *(const uint32_t*)&bs[nr * HP + k16 + 2 * t + 8];
                #pragma unroll
                for (int mi = 0; mi < 2; mi++)
                    mma_f16(c[mi][ni][0], c[mi][ni][1], c[mi][ni][2], c[mi][ni][3],
                            a[mi][0], a[mi][1], a[mi][2], a[mi][3], b0, b1);
            }
        }
    }

    // epilogue: fragment (mi,ni): rows rbase+8*half, cols col..col+1
    #pragma unroll
    for (int mi = 0; mi < 2; mi++) {
        const int rbase = bm * 128 + wm * 32 + mi * 16 + g;
        #pragma unroll
        for (int ni = 0; ni < 8; ni++) {
            const int col = bn * 128 + wn * 64 + ni * 8 + t * 2;
            #pragma unroll
            for (int half_ = 0; half_ < 2; half_++) {
                const int m = rbase + half_ * 8;
                float v0 = c[mi][ni][half_ * 2 + 0];
                float v1 = c[mi][ni][half_ * 2 + 1];
                if (EPI == 0) {
                    const int which = col >> 10, nn = col & 1023;
                    const int h = nn >> 6, d = nn & 63;
                    const int b = m >> 11, tt = m & 2047;
                    if (which == 0) { v0 *= 0.03125f; v1 *= 0.03125f; }
                    __half* dst = (which == 0) ? H0 : (which == 1 ? H1 : H2);
                    *(__half2*)&dst[(size_t)((b << 4) + h) * (TSEQ * HDIM)
                                    + tt * HDIM + d] = __floats2half2_rn(v0, v1);
                } else if (EPI == 1 || EPI == 3) {
                    size_t o = (size_t)m * N + col;
                    float2 r2 = *(const float2*)&residual[o];
                    *(float2*)&Cf[o] =
                        make_float2(v0 + bias[col] + r2.x, v1 + bias[col + 1] + r2.y);
                } else {
                    size_t o = (size_t)m * N + col;
                    float t0 = v0 + bias[col], t1 = v1 + bias[col + 1];
                    *(__half2*)&H0[o] = __floats2half2_rn(
                        t0 > 0.f ? t0 : 0.f, t1 > 0.f ? t1 : 0.f);
                }
            }
        }
    }
}

// ---------------------------------------------------------------------------
// Flash attention, fp16 mma.sync.m16n8k16. Block = 256 queries, 8 warps,
// warp tile 32 rows x 64 keys. Q pre-scaled. fp16 smem, fp32 accum.
// ---------------------------------------------------------------------------
#define BLKQ 256
#define AQP 72          // pitch in halfs (144B rows; conflict-free, 16B aligned)
#define ATTN_SMEM_BYTES ((BLKQ*AQP*2 + 64*AQP*2) * 2)   // Qs+Ps+Ks+Vs halfs *2B

__global__ void __launch_bounds__(256, 1) attn_kernel(
    const __half* __restrict__ Q, const __half* __restrict__ K,
    const __half* __restrict__ V, __half* __restrict__ O)
{
    extern __shared__ __half asm_[];
    __half* Qs = asm_;                     // [256][72]
    __half* Ps = Qs + BLKQ * AQP;          // [256][72]
    __half* Ks = Ps + BLKQ * AQP;          // [64][72]
    __half* Vs = Ks + 64 * AQP;            // [64][72]
    const uint32_t vbase = smem_u32(Vs);

    const int tid  = threadIdx.x;
    const int w    = tid >> 5, lane = tid & 31;
    const int g    = lane >> 2, t = lane & 3;
    const int bh   = blockIdx.y;
    const int qt   = blockIdx.x;

    const __half* Qb = Q + ((size_t)bh * TSEQ + qt * BLKQ) * HDIM;
    const __half* Kb = K + (size_t)bh * TSEQ * HDIM;
    const __half* Vb = V + (size_t)bh * TSEQ * HDIM;

    // load Q tile (already scaled): 2048 16B-chunks, 8 per thread
    #pragma unroll
    for (int q = 0; q < 8; q++) {
        int f  = tid + 256 * q;
        int j  = f >> 3;
        int d8 = (f & 7) * 8;
        *(uint4*)&Qs[j * AQP + d8] = *(const uint4*)(Qb + (size_t)j * HDIM + d8);
    }

    float m_[2][2], l_[2][2], co[2][8][4];
    #pragma unroll
    for (int mi = 0; mi < 2; mi++)
        #pragma unroll
        for (int r = 0; r < 2; r++) { m_[mi][r] = -1e30f; l_[mi][r] = 0.f; }
    #pragma unroll
    for (int mi = 0; mi < 2; mi++)
        #pragma unroll
        for (int ni = 0; ni < 8; ni++)
            #pragma unroll
            for (int q = 0; q < 4; q++) co[mi][ni][q] = 0.f;

    const int rowb = w * 32;

    for (int kt = 0; kt < TSEQ / 64; kt++) {
        __syncthreads();
        #pragma unroll
        for (int q = 0; q < 2; q++) {
            int f  = tid + 256 * q;
            int j  = f >> 3;
            int d8 = (f & 7) * 8;
            *(uint4*)&Ks[j * AQP + d8] =
                *(const uint4*)(Kb + (size_t)(kt * 64 + j) * HDIM + d8);
            *(uint4*)&Vs[j * AQP + d8] =
                *(const uint4*)(Vb + (size_t)(kt * 64 + j) * HDIM + d8);
        }
        __syncthreads();

        // S = Q K^T
        float cs[2][8][4];
        #pragma unroll
        for (int mi = 0; mi < 2; mi++)
            #pragma unroll
            for (int ni = 0; ni < 8; ni++)
                #pragma unroll
                for (int q = 0; q < 4; q++) cs[mi][ni][q] = 0.f;

        #pragma unroll
        for (int ks = 0; ks < 4; ks++) {
            const int k16 = ks * 16;
            uint32_t a[2][4];
            #pragma unroll
            for (int mi = 0; mi < 2; mi++) {
                const int r = rowb + mi * 16 + g;
                a[mi][0] = *(const uint32_t*)&Qs[(r    ) * AQP + k16 + 2 * t];
                a[mi][1] = *(const uint32_t*)&Qs[(r + 8) * AQP + k16 + 2 * t];
                a[mi][2] = *(const uint32_t*)&Qs[(r    ) * AQP + k16 + 2 * t + 8];
                a[mi][3] = *(const uint32_t*)&Qs[(r + 8) * AQP + k16 + 2 * t + 8];
            }
            #pragma unroll
            for (int ni = 0; ni < 8; ni++) {
                const int nr = ni * 8 + g;
                uint32_t b0 = *(const uint32_t*)&Ks[nr * AQP + k16 + 2 * t];
                uint32_t b1 = *(const uint32_t*)&Ks[nr * AQP + k16 + 2 * t + 8];
                #pragma unroll
                for (int mi = 0; mi < 2; mi++)
                    mma_f16(cs[mi][ni][0], cs[mi][ni][1], cs[mi][ni][2], cs[mi][ni][3],
                            a[mi][0], a[mi][1], a[mi][2], a[mi][3], b0, b1);
            }
        }

        // online softmax
        #pragma unroll
        for (int mi = 0; mi < 2; mi++) {
            #pragma unroll
            for (int r = 0; r < 2; r++) {
                float mx = -1e30f;
                #pragma unroll
                for (int ni = 0; ni < 8; ni++)
                    mx = fmaxf(mx, fmaxf(cs[mi][ni][2*r], cs[mi][ni][2*r+1]));
                mx = fmaxf(mx, __shfl_xor_sync(0xffffffffu, mx, 1));
                mx = fmaxf(mx, __shfl_xor_sync(0xffffffffu, mx, 2));
                float mnew = fmaxf(m_[mi][r], mx);
                float corr = __expf(m_[mi][r] - mnew);
                m_[mi][r] = mnew;
                float rs = 0.f;
                #pragma unroll
                for (int ni = 0; ni < 8; ni++) {
                    float p0 = __expf(cs[mi][ni][2*r]   - mnew);
                    float p1 = __expf(cs[mi][ni][2*r+1] - mnew);
                    rs += p0 + p1;
                    cs[mi][ni][2*r]   = p0;
                    cs[mi][ni][2*r+1] = p1;
                }
                rs += __shfl_xor_sync(0xffffffffu, rs, 1);
                rs += __shfl_xor_sync(0xffffffffu, rs, 2);
                l_[mi][r] = l_[mi][r] * corr + rs;
                #pragma unroll
                for (int ni = 0; ni < 8; ni++) {
                    co[mi][ni][2*r]   *= corr;
                    co[mi][ni][2*r+1] *= corr;
                }
                const int row = rowb + mi * 16 + g + 8 * r;
                #pragma unroll
                for (int ni = 0; ni < 8; ni++)
                    *(__half2*)&Ps[row * AQP + ni * 8 + 2 * t] =
                        __floats2half2_rn(cs[mi][ni][2*r], cs[mi][ni][2*r+1]);
            }
        }
        __syncwarp();

        // O += P V   (V operand via ldmatrix.trans)
        #pragma unroll
        for (int ks = 0; ks < 4; ks++) {
            const int k16 = ks * 16;
            uint32_t a[2][4];
            #pragma unroll
            for (int mi = 0; mi < 2; mi++) {
                const int r = rowb + mi * 16 + g;
                a[mi][0] = *(const uint32_t*)&Ps[(r    ) * AQP + k16 + 2 * t];
                a[mi][1] = *(const uint32_t*)&Ps[(r + 8) * AQP + k16 + 2 * t];
                a[mi][2] = *(const uint32_t*)&Ps[(r    ) * AQP + k16 + 2 * t + 8];
                a[mi][3] = *(const uint32_t*)&Ps[(r + 8) * AQP + k16 + 2 * t + 8];
            }
            #pragma unroll
            for (int ni = 0; ni < 8; ni++) {
                uint32_t b0, b1;
                // rows k16 + (lane&15) of Vs, 16B at col ni*8
                uint32_t addr = vbase +
                    (uint32_t)(((k16 + (lane & 15)) * AQP + ni * 8) * 2);
                ldmx2t(b0, b1, addr);
                #pragma unroll
                for (int mi = 0; mi < 2; mi++)
                    mma_f16(co[mi][ni][0], co[mi][ni][1], co[mi][ni][2], co[mi][ni][3],
                            a[mi][0], a[mi][1], a[mi][2], a[mi][3], b0, b1);
            }
        }
    }

    const int b = bh >> 4, h = bh & 15;
    #pragma unroll
    for (int mi = 0; mi < 2; mi++) {
        #pragma unroll
        for (int r = 0; r < 2; r++) {
            float inv = 1.0f / l_[mi][r];
            int row = qt * BLKQ + rowb + mi * 16 + g + 8 * r;
            #pragma unroll
            for (int ni = 0; ni < 8; ni++) {
                int d = ni * 8 + 2 * t;
                *(__half2*)&O[((size_t)(b * TSEQ + row)) * CDIM + h * HDIM + d] =
                    __floats2half2_rn(co[mi][ni][2*r] * inv, co[mi][ni][2*r+1] * inv);
            }
        }
    }
}

// ---------------------------------------------------------------------------
extern "C" void kernel_launch(void* const* d_in, const int* in_sizes, int n_in,
                              void* d_out, int out_size)
{
    const float* x      = (const float*)d_in[0];
    const float* wq     = (const float*)d_in[1];
    const float* wk     = (const float*)d_in[2];
    const float* wv     = (const float*)d_in[3];
    const float* w_proj = (const float*)d_in[4];
    const float* b_proj = (const float*)d_in[5];
    const float* w1     = (const float*)d_in[6];
    const float* b1     = (const float*)d_in[7];
    const float* w2     = (const float*)d_in[8];
    const float* b2     = (const float*)d_in[9];
    const float* g1     = (const float*)d_in[10];
    const float* be1    = (const float*)d_in[11];
    const float* g2     = (const float*)d_in[12];
    const float* be2    = (const float*)d_in[13];
    float* out = (float*)d_out;

    float  *px1;
    __half *pq, *pk, *pv, *ph, *ph2, *patt, *pff, *pwqkvT, *pwprojT, *pw1T, *pw2T;
    cudaGetSymbolAddress((void**)&pq,      g_q);
    cudaGetSymbolAddress((void**)&pk,      g_k);
    cudaGetSymbolAddress((void**)&pv,      g_v);
    cudaGetSymbolAddress((void**)&px1,     g_x1);
    cudaGetSymbolAddress((void**)&ph,      g_h);
    cudaGetSymbolAddress((void**)&ph2,     g_h2);
    cudaGetSymbolAddress((void**)&patt,    g_att);
    cudaGetSymbolAddress((void**)&pff,     g_ff);
    cudaGetSymbolAddress((void**)&pwqkvT,  g_wqkvT);
    cudaGetSymbolAddress((void**)&pwprojT, g_wprojT);
    cudaGetSymbolAddress((void**)&pw1T,    g_w1T);
    cudaGetSymbolAddress((void**)&pw2T,    g_w2T);

    cudaFuncSetAttribute(attn_kernel,
                         cudaFuncAttributeMaxDynamicSharedMemorySize, ATTN_SMEM_BYTES);
    cudaFuncSetAttribute(hgemm_kernel<0>,
                         cudaFuncAttributeMaxDynamicSharedMemorySize, HGEMM_SMEM);
    cudaFuncSetAttribute(hgemm_kernel<1>,
                         cudaFuncAttributeMaxDynamicSharedMemorySize, HGEMM_SMEM);
    cudaFuncSetAttribute(hgemm_kernel<2>,
                         cudaFuncAttributeMaxDynamicSharedMemorySize, HGEMM_SMEM);
    cudaFuncSetAttribute(hgemm_kernel<3>,
                         cudaFuncAttributeMaxDynamicSharedMemorySize, HGEMM_SMEM);

    // 0) weight prep (fp16, [N][K])
    pack_qkv_t<<<dim3(32, 2, 48), 256>>>(wq, wk, wv, pwqkvT);
    transpose_to_half<<<dim3(CDIM / 32, CDIM / 32), 256>>>(w_proj, pwprojT, CDIM, CDIM);
    transpose_to_half<<<dim3(FFDIM / 32, CDIM / 32), 256>>>(w1, pw1T, CDIM, FFDIM);
    transpose_to_half<<<dim3(CDIM / 32, FFDIM / 32), 256>>>(w2, pw2T, FFDIM, CDIM);

    // 1) ln1 -> fp16
    ln_kernel<<<BT, 256>>>(x, g1, be1, ph);
    // 2) QKV gemm -> fp16 q(scaled)/k/v scatter
    hgemm_kernel<0><<<dim3(3 * CDIM / 128, BT / 128), 256, HGEMM_SMEM>>>(
        ph, pwqkvT, BT, 3 * CDIM, CDIM, nullptr, nullptr, nullptr, pq, pk, pv);
    // 3) attention -> fp16 att
    attn_kernel<<<dim3(TSEQ / BLKQ, 4 * NHEAD), 256, ATTN_SMEM_BYTES>>>(
        pq, pk, pv, patt);
    // 4) proj + bias + residual(x) -> fp32 x1
    hgemm_kernel<1><<<dim3(CDIM / 128, BT / 128), 256, HGEMM_SMEM>>>(
        patt, pwprojT, BT, CDIM, CDIM, b_proj, x, px1, nullptr, nullptr, nullptr);
    // 5) ln2 -> fp16
    ln_kernel<<<BT, 256>>>(px1, g2, be2, ph2);
    // 6) ffn1: relu(h2 @ w1 + b1) -> fp16 ff
    hgemm_kernel<2><<<dim3(FFDIM / 128, BT / 128), 256, HGEMM_SMEM>>>(
        ph2, pw1T, BT, FFDIM, CDIM, b1, nullptr, nullptr, pff, nullptr, nullptr);
    // 7) ffn2: ff @ w2 + b2 + x1 -> fp32 out
    hgemm_kernel<3><<<dim3(CDIM / 128, BT / 128), 256, HGEMM_SMEM>>>(
        pff, pw2T, BT, CDIM, FFDIM, b2, px1, out, nullptr, nullptr, nullptr);
}

// round 7
// speedup vs baseline: 5.9501x; 1.2162x over previous
#include <cuda_runtime.h>
#include <cuda_fp16.h>
#include <math.h>
#include <stdint.h>

// ---------------------------------------------------------------------------
// Encoder block, fp32 IO. All tensor math on fp16 mma.sync.m16n8k16 (fp32 acc).
// Round 7: ldmatrix operand loads, register-resident P, cp.async K/V pipeline.
// ---------------------------------------------------------------------------

#define BT      8192
#define CDIM    1024
#define FFDIM   4096
#define NHEAD   16
#define HDIM    64
#define TSEQ    2048

__device__ __half g_q   [BT * CDIM];   // [B,H,T,D] fp16 (pre-scaled by C^-0.5)
__device__ __half g_k   [BT * CDIM];
__device__ __half g_v   [BT * CDIM];
__device__ float  g_x1  [BT * CDIM];
__device__ __half g_h   [BT * CDIM];
__device__ __half g_h2  [BT * CDIM];
__device__ __half g_att [BT * CDIM];
__device__ __half g_ff  [BT * FFDIM];
__device__ __half g_wqkvT [3 * CDIM * CDIM];
__device__ __half g_wprojT[CDIM * CDIM];
__device__ __half g_w1T   [FFDIM * CDIM];
__device__ __half g_w2T   [CDIM * FFDIM];

// ---------------------------------------------------------------------------
__device__ __forceinline__ void cp16(uint32_t smem, const void* gmem) {
    asm volatile("cp.async.cg.shared.global [%0], [%1], 16;" :: "r"(smem), "l"(gmem));
}
__device__ __forceinline__ void cp_commit() {
    asm volatile("cp.async.commit_group;" ::: "memory");
}
template<int N>
__device__ __forceinline__ void cp_wait() {
    asm volatile("cp.async.wait_group %0;" :: "n"(N) : "memory");
}
__device__ __forceinline__ uint32_t smem_u32(const void* p) {
    uint32_t a;
    asm("{ .reg .u64 t; cvta.to.shared.u64 t, %1; cvt.u32.u64 %0, t; }"
        : "=r"(a) : "l"(p));
    return a;
}
__device__ __forceinline__ void mma_f16(
    float& c0, float& c1, float& c2, float& c3,
    uint32_t a0, uint32_t a1, uint32_t a2, uint32_t a3,
    uint32_t b0, uint32_t b1)
{
    asm volatile(
        "mma.sync.aligned.m16n8k16.row.col.f32.f16.f16.f32 "
        "{%0,%1,%2,%3}, {%4,%5,%6,%7}, {%8,%9}, {%0,%1,%2,%3};"
        : "+f"(c0), "+f"(c1), "+f"(c2), "+f"(c3)
        : "r"(a0), "r"(a1), "r"(a2), "r"(a3), "r"(b0), "r"(b1));
}
__device__ __forceinline__ void ldmx4(
    uint32_t& r0, uint32_t& r1, uint32_t& r2, uint32_t& r3, uint32_t addr)
{
    asm volatile("ldmatrix.sync.aligned.m8n8.x4.shared.b16 {%0,%1,%2,%3}, [%4];"
                 : "=r"(r0), "=r"(r1), "=r"(r2), "=r"(r3) : "r"(addr));
}
__device__ __forceinline__ void ldmx4t(
    uint32_t& r0, uint32_t& r1, uint32_t& r2, uint32_t& r3, uint32_t addr)
{
    asm volatile("ldmatrix.sync.aligned.m8n8.x4.trans.shared.b16 {%0,%1,%2,%3}, [%4];"
                 : "=r"(r0), "=r"(r1), "=r"(r2), "=r"(r3) : "r"(addr));
}
__device__ __forceinline__ uint32_t pack_h2(float a, float b) {
    __half2 h = __floats2half2_rn(a, b);
    return *(uint32_t*)&h;
}

// ---------------------------------------------------------------------------
// Weight prep
// ---------------------------------------------------------------------------
__global__ void __launch_bounds__(256) transpose_to_half(
    const float* __restrict__ src, __half* __restrict__ dst, int K, int N)
{
    __shared__ float tile[32][33];
    int n0 = blockIdx.x * 32, k0 = blockIdx.y * 32;
    int tx = threadIdx.x & 31, ty = threadIdx.x >> 5;
    #pragma unroll
    for (int r = ty; r < 32; r += 8)
        tile[r][tx] = src[(size_t)(k0 + r) * N + n0 + tx];
    __syncthreads();
    #pragma unroll
    for (int r = ty; r < 32; r += 8)
        dst[(size_t)(n0 + r) * K + k0 + tx] = __float2half(tile[tx][r]);
}

__global__ void __launch_bounds__(256) pack_qkv_t(
    const float* __restrict__ wq, const float* __restrict__ wk,
    const float* __restrict__ wv, __half* __restrict__ dst)
{
    __shared__ float tile[32][33];
    int wh = blockIdx.z;
    int which = wh >> 4, h = wh & 15;
    const float* w = (which == 0) ? wq : (which == 1 ? wk : wv);
    int c0 = blockIdx.x * 32, d0 = blockIdx.y * 32;
    int tx = threadIdx.x & 31, ty = threadIdx.x >> 5;
    #pragma unroll
    for (int r = ty; r < 32; r += 8)
        tile[r][tx] = w[(size_t)(h * CDIM + c0 + r) * HDIM + d0 + tx];
    __syncthreads();
    #pragma unroll
    for (int r = ty; r < 32; r += 8)
        dst[(size_t)(which * 1024 + h * 64 + d0 + r) * CDIM + c0 + tx] =
            __float2half(tile[tx][r]);
}

// ---------------------------------------------------------------------------
// LayerNorm fp32 -> fp16
// ---------------------------------------------------------------------------
__global__ void __launch_bounds__(256) ln_kernel(
    const float* __restrict__ x, const float* __restrict__ gamma,
    const float* __restrict__ beta, __half* __restrict__ out)
{
    __shared__ float red[8];
    int row = blockIdx.x;
    const float4* xr = (const float4*)(x + (size_t)row * CDIM);
    float4 v = xr[threadIdx.x];

    float s = v.x + v.y + v.z + v.w;
    #pragma unroll
    for (int o = 16; o > 0; o >>= 1) s += __shfl_xor_sync(0xffffffffu, s, o);
    if ((threadIdx.x & 31) == 0) red[threadIdx.x >> 5] = s;
    __syncthreads();
    float tot = 0.f;
    #pragma unroll
    for (int i = 0; i < 8; i++) tot += red[i];
    float mu = tot * (1.0f / 1024.0f);

    float dx = v.x - mu, dy = v.y - mu, dz = v.z - mu, dw = v.w - mu;
    float sq = dx*dx + dy*dy + dz*dz + dw*dw;
    #pragma unroll
    for (int o = 16; o > 0; o >>= 1) sq += __shfl_xor_sync(0xffffffffu, sq, o);
    __syncthreads();
    if ((threadIdx.x & 31) == 0) red[threadIdx.x >> 5] = sq;
    __syncthreads();
    float vt = 0.f;
    #pragma unroll
    for (int i = 0; i < 8; i++) vt += red[i];
    float rstd = rsqrtf(vt * (1.0f / 1024.0f) + 1e-5f);

    float4 g4 = ((const float4*)gamma)[threadIdx.x];
    float4 b4 = ((const float4*)beta)[threadIdx.x];
    __half2* orow = (__half2*)(out + (size_t)row * CDIM);
    orow[threadIdx.x * 2 + 0] =
        __floats2half2_rn(dx * rstd * g4.x + b4.x, dy * rstd * g4.y + b4.y);
    orow[threadIdx.x * 2 + 1] =
        __floats2half2_rn(dz * rstd * g4.z + b4.z, dw * rstd * g4.w + b4.w);
}

// ---------------------------------------------------------------------------
// fp16 GEMM, 4-stage cp.async, ldmatrix operand loads.
// ---------------------------------------------------------------------------
#define HP 40
#define HSTG (128 * HP)
#define HSTAGES 4
#define HGEMM_SMEM (HSTAGES * 2 * HSTG * 2)

template<int EPI>
__global__ void __launch_bounds__(256, 2) hgemm_kernel(
    const __half* __restrict__ A, const __half* __restrict__ B,
    int M, int N, int K,
    const float* __restrict__ bias, const float* __restrict__ residual,
    float* __restrict__ Cf,
    __half* __restrict__ H0, __half* __restrict__ H1, __half* __restrict__ H2)
{
    extern __shared__ __half hsm[];
    const uint32_t sa_u32 = smem_u32(hsm);
    const uint32_t sb_u32 = sa_u32 + HSTAGES * HSTG * 2;

    const int tid  = threadIdx.x;
    const int bn   = blockIdx.x, bm = blockIdx.y;
    const int warp = tid >> 5, lane = tid & 31;
    const int wm   = warp & 3, wn = warp >> 2;

    // copy mapping
    const int crow = tid >> 1;
    const int ccol = (tid & 1) * 16;
    const __half* Ag = A + (size_t)(bm * 128 + crow) * K + ccol;
    const __half* Bg = B + (size_t)(bn * 128 + crow) * K + ccol;
    const uint32_t sA = sa_u32 + (crow * HP + ccol) * 2;
    const uint32_t sB = sb_u32 + (crow * HP + ccol) * 2;

    // ldmatrix fragment address offsets (bytes within a stage)
    uint32_t aoff[2], boff[4];
    #pragma unroll
    for (int mi = 0; mi < 2; mi++) {
        int row = wm * 32 + mi * 16 + (lane & 15);
        aoff[mi] = (uint32_t)(row * HP + 8 * (lane >> 4)) * 2;
    }
    #pragma unroll
    for (int p = 0; p < 4; p++) {
        int row = wn * 64 + p * 16 + (lane & 7) + 8 * (lane >> 4);
        boff[p] = (uint32_t)(row * HP + 8 * ((lane >> 3) & 1)) * 2;
    }

    float c[2][8][4];
    #pragma unroll
    for (int i = 0; i < 2; i++)
        #pragma unroll
        for (int j = 0; j < 8; j++)
            #pragma unroll
            for (int q = 0; q < 4; q++) c[i][j][q] = 0.f;

    const int nk = K >> 5;

    auto issue = [&](int kt) {
        const uint32_t st = (uint32_t)(kt & (HSTAGES - 1)) * HSTG * 2;
        const __half* ag = Ag + (size_t)kt * 32;
        const __half* bg = Bg + (size_t)kt * 32;
        cp16(sA + st, ag);
        cp16(sA + st + 16, ag + 8);
        cp16(sB + st, bg);
        cp16(sB + st + 16, bg + 8);
    };

    #pragma unroll
    for (int s = 0; s < HSTAGES - 1; s++) { issue(s); cp_commit(); }

    for (int kt = 0; kt < nk; kt++) {
        cp_wait<HSTAGES - 2>();
        __syncthreads();
        if (kt + HSTAGES - 1 < nk) issue(kt + HSTAGES - 1);
        cp_commit();

        const uint32_t st = (uint32_t)(kt & (HSTAGES - 1)) * HSTG * 2;
        #pragma unroll
        for (int ks = 0; ks < 2; ks++) {
            const uint32_t kb = st + ks * 32;   // k16*2 bytes
            uint32_t a[2][4];
            ldmx4(a[0][0], a[0][1], a[0][2], a[0][3], sa_u32 + aoff[0] + kb);
            ldmx4(a[1][0], a[1][1], a[1][2], a[1][3], sa_u32 + aoff[1] + kb);
            #pragma unroll
            for (int p = 0; p < 4; p++) {
                uint32_t b0, b1, b2, b3;
                ldmx4(b0, b1, b2, b3, sb_u32 + boff[p] + kb);
                mma_f16(c[0][2*p][0], c[0][2*p][1], c[0][2*p][2], c[0][2*p][3],
                        a[0][0], a[0][1], a[0][2], a[0][3], b0, b1);
                mma_f16(c[1][2*p][0], c[1][2*p][1], c[1][2*p][2], c[1][2*p][3],
                        a[1][0], a[1][1], a[1][2], a[1][3], b0, b1);
                mma_f16(c[0][2*p+1][0], c[0][2*p+1][1], c[0][2*p+1][2], c[0][2*p+1][3],
                        a[0][0], a[0][1], a[0][2], a[0][3], b2, b3);
                mma_f16(c[1][2*p+1][0], c[1][2*p+1][1], c[1][2*p+1][2], c[1][2*p+1][3],
                        a[1][0], a[1][1], a[1][2], a[1][3], b2, b3);
            }
        }
    }

    const int g = lane >> 2, t = lane & 3;
    #pragma unroll
    for (int mi = 0; mi < 2; mi++) {
        const int rbase = bm * 128 + wm * 32 + mi * 16 + g;
        #pragma unroll
        for (int ni = 0; ni < 8; ni++) {
            const int col = bn * 128 + wn * 64 + ni * 8 + t * 2;
            #pragma unroll
            for (int half_ = 0; half_ < 2; half_++) {
                const int m = rbase + half_ * 8;
                float v0 = c[mi][ni][half_ * 2 + 0];
                float v1 = c[mi][ni][half_ * 2 + 1];
                if (EPI == 0) {
                    const int which = col >> 10, nn = col & 1023;
                    const int h = nn >> 6, d = nn & 63;
                    const int b = m >> 11, tt = m & 2047;
                    if (which == 0) { v0 *= 0.03125f; v1 *= 0.03125f; }
                    __half* dst = (which == 0) ? H0 : (which == 1 ? H1 : H2);
                    *(__half2*)&dst[(size_t)((b << 4) + h) * (TSEQ * HDIM)
                                    + tt * HDIM + d] = __floats2half2_rn(v0, v1);
                } else if (EPI == 1 || EPI == 3) {
                    size_t o = (size_t)m * N + col;
                    float2 r2 = *(const float2*)&residual[o];
                    *(float2*)&Cf[o] =
                        make_float2(v0 + bias[col] + r2.x, v1 + bias[col + 1] + r2.y);
                } else {
                    size_t o = (size_t)m * N + col;
                    float t0 = v0 + bias[col], t1 = v1 + bias[col + 1];
                    *(__half2*)&H0[o] = __floats2half2_rn(
                        t0 > 0.f ? t0 : 0.f, t1 > 0.f ? t1 : 0.f);
                }
            }
        }
    }
}

// ---------------------------------------------------------------------------
// Flash attention: Q in registers, P in registers, ldmatrix K/V,
// cp.async double-buffered K/V tiles. 256 queries/CTA, 8 warps.
// ---------------------------------------------------------------------------
#define BLKQ 256
#define AQP 72
#define QS_BYTES  (BLKQ * AQP * 2)          // 36864
#define KV_BYTES  (64 * AQP * 2)            // 9216 per tile
#define KVSTRIDE  (2 * KV_BYTES)            // K+V per buffer
#define ATTN_SMEM_BYTES (QS_BYTES + 2 * KVSTRIDE)   // 73728

__global__ void __launch_bounds__(256, 1) attn_kernel(
    const __half* __restrict__ Q, const __half* __restrict__ K,
    const __half* __restrict__ V, __half* __restrict__ O)
{
    extern __shared__ __half asm_[];
    const uint32_t qs_u32 = smem_u32(asm_);
    const uint32_t kv_u32 = qs_u32 + QS_BYTES;

    const int tid  = threadIdx.x;
    const int w    = tid >> 5, lane = tid & 31;
    const int g    = lane >> 2, t = lane & 3;
    const int bh   = blockIdx.y;
    const int qt   = blockIdx.x;
    const int rowb = w * 32;

    const __half* Qb = Q + ((size_t)bh * TSEQ + qt * BLKQ) * HDIM;
    const __half* Kb = K + (size_t)bh * TSEQ * HDIM;
    const __half* Vb = V + (size_t)bh * TSEQ * HDIM;

    // K/V tile fill (cp.async): 512 16B chunks each; 2 per thread per tensor
    auto issue = [&](int kt) {
        const uint32_t base = kv_u32 + (uint32_t)(kt & 1) * KVSTRIDE;
        const __half* kg = Kb + (size_t)kt * 64 * HDIM;
        const __half* vg = Vb + (size_t)kt * 64 * HDIM;
        #pragma unroll
        for (int q = 0; q < 2; q++) {
            int cidx = tid + 256 * q;
            int row = cidx >> 3, col = (cidx & 7) * 8;
            uint32_t so = (uint32_t)(row * AQP + col) * 2;
            cp16(base + so, kg + (size_t)row * HDIM + col);
            cp16(base + KV_BYTES + so, vg + (size_t)row * HDIM + col);
        }
    };

    // load Q tile -> smem (coalesced), then to register fragments
    #pragma unroll
    for (int q = 0; q < 8; q++) {
        int f  = tid + 256 * q;
        int j  = f >> 3;
        int d8 = (f & 7) * 8;
        *(uint4*)&asm_[j * AQP + d8] = *(const uint4*)(Qb + (size_t)j * HDIM + d8);
    }
    issue(0);
    cp_commit();
    __syncthreads();

    uint32_t qa[4][2][4];
    {
        uint32_t qoff[2];
        #pragma unroll
        for (int mi = 0; mi < 2; mi++) {
            int row = rowb + mi * 16 + (lane & 15);
            qoff[mi] = (uint32_t)(row * AQP + 8 * (lane >> 4)) * 2;
        }
        #pragma unroll
        for (int ks = 0; ks < 4; ks++) {
            #pragma unroll
            for (int mi = 0; mi < 2; mi++)
                ldmx4(qa[ks][mi][0], qa[ks][mi][1], qa[ks][mi][2], qa[ks][mi][3],
                      qs_u32 + qoff[mi] + ks * 32);
        }
    }

    // fragment address offsets into K/V tiles
    uint32_t koff[4], voff[4];
    #pragma unroll
    for (int p = 0; p < 4; p++) {
        int krow = p * 16 + (lane & 7) + 8 * (lane >> 4);
        koff[p] = (uint32_t)(krow * AQP + 8 * ((lane >> 3) & 1)) * 2;
        voff[p] = (uint32_t)((lane & 15) * AQP + p * 16 + 8 * (lane >> 4)) * 2;
    }

    float m_[2][2], l_[2][2], co[2][8][4];
    #pragma unroll
    for (int mi = 0; mi < 2; mi++)
        #pragma unroll
        for (int r = 0; r < 2; r++) { m_[mi][r] = -1e30f; l_[mi][r] = 0.f; }
    #pragma unroll
    for (int mi = 0; mi < 2; mi++)
        #pragma unroll
        for (int ni = 0; ni < 8; ni++)
            #pragma unroll
            for (int q = 0; q < 4; q++) co[mi][ni][q] = 0.f;

    const int nkt = TSEQ / 64;
    for (int kt = 0; kt < nkt; kt++) {
        if (kt > 0) __syncthreads();      // all warps done with buffer (kt+1)&1
        if (kt + 1 < nkt) {
            issue(kt + 1);
            cp_commit();
            cp_wait<1>();
        } else {
            cp_wait<0>();
        }
        __syncthreads();                  // buffer kt&1 visible to all

        const uint32_t kbase = kv_u32 + (uint32_t)(kt & 1) * KVSTRIDE;
        const uint32_t vbase = kbase + KV_BYTES;

        // ---- S = Q K^T ----
        float cs[2][8][4];
        #pragma unroll
        for (int mi = 0; mi < 2; mi++)
            #pragma unroll
            for (int ni = 0; ni < 8; ni++)
                #pragma unroll
                for (int q = 0; q < 4; q++) cs[mi][ni][q] = 0.f;

        #pragma unroll
        for (int ks = 0; ks < 4; ks++) {
            #pragma unroll
            for (int p = 0; p < 4; p++) {
                uint32_t b0, b1, b2, b3;
                ldmx4(b0, b1, b2, b3, kbase + koff[p] + ks * 32);
                mma_f16(cs[0][2*p][0], cs[0][2*p][1], cs[0][2*p][2], cs[0][2*p][3],
                        qa[ks][0][0], qa[ks][0][1], qa[ks][0][2], qa[ks][0][3], b0, b1);
                mma_f16(cs[1][2*p][0], cs[1][2*p][1], cs[1][2*p][2], cs[1][2*p][3],
                        qa[ks][1][0], qa[ks][1][1], qa[ks][1][2], qa[ks][1][3], b0, b1);
                mma_f16(cs[0][2*p+1][0], cs[0][2*p+1][1], cs[0][2*p+1][2], cs[0][2*p+1][3],
                        qa[ks][0][0], qa[ks][0][1], qa[ks][0][2], qa[ks][0][3], b2, b3);
                mma_f16(cs[1][2*p+1][0], cs[1][2*p+1][1], cs[1][2*p+1][2], cs[1][2*p+1][3],
                        qa[ks][1][0], qa[ks][1][1], qa[ks][1][2], qa[ks][1][3], b2, b3);
            }
        }

        // ---- online softmax (P stays in registers) ----
        #pragma unroll
        for (int mi = 0; mi < 2; mi++) {
            #pragma unroll
            for (int r = 0; r < 2; r++) {
                float mx = -1e30f;
                #pragma unroll
                for (int ni = 0; ni < 8; ni++)
                    mx = fmaxf(mx, fmaxf(cs[mi][ni][2*r], cs[mi][ni][2*r+1]));
                mx = fmaxf(mx, __shfl_xor_sync(0xffffffffu, mx, 1));
                mx = fmaxf(mx, __shfl_xor_sync(0xffffffffu, mx, 2));
                float mnew = fmaxf(m_[mi][r], mx);
                float corr = __expf(m_[mi][r] - mnew);
                m_[mi][r] = mnew;
                float rs = 0.f;
                #pragma unroll
                for (int ni = 0; ni < 8; ni++) {
                    float p0 = __expf(cs[mi][ni][2*r]   - mnew);
                    float p1 = __expf(cs[mi][ni][2*r+1] - mnew);
                    rs += p0 + p1;
                    cs[mi][ni][2*r]   = p0;
                    cs[mi][ni][2*r+1] = p1;
                }
                rs += __shfl_xor_sync(0xffffffffu, rs, 1);
                rs += __shfl_xor_sync(0xffffffffu, rs, 2);
                l_[mi][r] = l_[mi][r] * corr + rs;
                #pragma unroll
                for (int ni = 0; ni < 8; ni++) {
                    co[mi][ni][2*r]   *= corr;
                    co[mi][ni][2*r+1] *= corr;
                }
            }
        }

        // ---- P fragments directly from cs registers ----
        uint32_t pa[4][2][4];
        #pragma unroll
        for (int ks = 0; ks < 4; ks++) {
            #pragma unroll
            for (int mi = 0; mi < 2; mi++) {
                pa[ks][mi][0] = pack_h2(cs[mi][2*ks][0],   cs[mi][2*ks][1]);
                pa[ks][mi][1] = pack_h2(cs[mi][2*ks][2],   cs[mi][2*ks][3]);
                pa[ks][mi][2] = pack_h2(cs[mi][2*ks+1][0], cs[mi][2*ks+1][1]);
                pa[ks][mi][3] = pack_h2(cs[mi][2*ks+1][2], cs[mi][2*ks+1][3]);
            }
        }

        // ---- O += P V ----
        #pragma unroll
        for (int ks = 0; ks < 4; ks++) {
            #pragma unroll
            for (int p = 0; p < 4; p++) {
                uint32_t b0, b1, b2, b3;
                ldmx4t(b0, b1, b2, b3, vbase + voff[p] + (uint32_t)(ks * 16 * AQP) * 2);
                mma_f16(co[0][2*p][0], co[0][2*p][1], co[0][2*p][2], co[0][2*p][3],
                        pa[ks][0][0], pa[ks][0][1], pa[ks][0][2], pa[ks][0][3], b0, b1);
                mma_f16(co[1][2*p][0], co[1][2*p][1], co[1][2*p][2], co[1][2*p][3],
                        pa[ks][1][0], pa[ks][1][1], pa[ks][1][2], pa[ks][1][3], b0, b1);
                mma_f16(co[0][2*p+1][0], co[0][2*p+1][1], co[0][2*p+1][2], co[0][2*p+1][3],
                        pa[ks][0][0], pa[ks][0][1], pa[ks][0][2], pa[ks][0][3], b2, b3);
                mma_f16(co[1][2*p+1][0], co[1][2*p+1][1], co[1][2*p+1][2], co[1][2*p+1][3],
                        pa[ks][1][0], pa[ks][1][1], pa[ks][1][2], pa[ks][1][3], b2, b3);
            }
        }
    }

    const int b = bh >> 4, h = bh & 15;
    #pragma unroll
    for (int mi = 0; mi < 2; mi++) {
        #pragma unroll
        for (int r = 0; r < 2; r++) {
            float inv = 1.0f / l_[mi][r];
            int row = qt * BLKQ + rowb + mi * 16 + g + 8 * r;
            #pragma unroll
            for (int ni = 0; ni < 8; ni++) {
                int d = ni * 8 + 2 * t;
                *(__half2*)&O[((size_t)(b * TSEQ + row)) * CDIM + h * HDIM + d] =
                    __floats2half2_rn(co[mi][ni][2*r] * inv, co[mi][ni][2*r+1] * inv);
            }
        }
    }
}

// ---------------------------------------------------------------------------
extern "C" void kernel_launch(void* const* d_in, const int* in_sizes, int n_in,
                              void* d_out, int out_size)
{
    const float* x      = (const float*)d_in[0];
    const float* wq     = (const float*)d_in[1];
    const float* wk     = (const float*)d_in[2];
    const float* wv     = (const float*)d_in[3];
    const float* w_proj = (const float*)d_in[4];
    const float* b_proj = (const float*)d_in[5];
    const float* w1     = (const float*)d_in[6];
    const float* b1     = (const float*)d_in[7];
    const float* w2     = (const float*)d_in[8];
    const float* b2     = (const float*)d_in[9];
    const float* g1     = (const float*)d_in[10];
    const float* be1    = (const float*)d_in[11];
    const float* g2     = (const float*)d_in[12];
    const float* be2    = (const float*)d_in[13];
    float* out = (float*)d_out;

    float  *px1;
    __half *pq, *pk, *pv, *ph, *ph2, *patt, *pff, *pwqkvT, *pwprojT, *pw1T, *pw2T;
    cudaGetSymbolAddress((void**)&pq,      g_q);
    cudaGetSymbolAddress((void**)&pk,      g_k);
    cudaGetSymbolAddress((void**)&pv,      g_v);
    cudaGetSymbolAddress((void**)&px1,     g_x1);
    cudaGetSymbolAddress((void**)&ph,      g_h);
    cudaGetSymbolAddress((void**)&ph2,     g_h2);
    cudaGetSymbolAddress((void**)&patt,    g_att);
    cudaGetSymbolAddress((void**)&pff,     g_ff);
    cudaGetSymbolAddress((void**)&pwqkvT,  g_wqkvT);
    cudaGetSymbolAddress((void**)&pwprojT, g_wprojT);
    cudaGetSymbolAddress((void**)&pw1T,    g_w1T);
    cudaGetSymbolAddress((void**)&pw2T,    g_w2T);

    cudaFuncSetAttribute(attn_kernel,
                         cudaFuncAttributeMaxDynamicSharedMemorySize, ATTN_SMEM_BYTES);
    cudaFuncSetAttribute(hgemm_kernel<0>,
                         cudaFuncAttributeMaxDynamicSharedMemorySize, HGEMM_SMEM);
    cudaFuncSetAttribute(hgemm_kernel<1>,
                         cudaFuncAttributeMaxDynamicSharedMemorySize, HGEMM_SMEM);
    cudaFuncSetAttribute(hgemm_kernel<2>,
                         cudaFuncAttributeMaxDynamicSharedMemorySize, HGEMM_SMEM);
    cudaFuncSetAttribute(hgemm_kernel<3>,
                         cudaFuncAttributeMaxDynamicSharedMemorySize, HGEMM_SMEM);

    // 0) weight prep (fp16, [N][K])
    pack_qkv_t<<<dim3(32, 2, 48), 256>>>(wq, wk, wv, pwqkvT);
    transpose_to_half<<<dim3(CDIM / 32, CDIM / 32), 256>>>(w_proj, pwprojT, CDIM, CDIM);
    transpose_to_half<<<dim3(FFDIM / 32, CDIM / 32), 256>>>(w1, pw1T, CDIM, FFDIM);
    transpose_to_half<<<dim3(CDIM / 32, FFDIM / 32), 256>>>(w2, pw2T, FFDIM, CDIM);

    // 1) ln1 -> fp16
    ln_kernel<<<BT, 256>>>(x, g1, be1, ph);
    // 2) QKV gemm -> fp16 q(scaled)/k/v scatter
    hgemm_kernel<0><<<dim3(3 * CDIM / 128, BT / 128), 256, HGEMM_SMEM>>>(
        ph, pwqkvT, BT, 3 * CDIM, CDIM, nullptr, nullptr, nullptr, pq, pk, pv);
    // 3) attention -> fp16 att
    attn_kernel<<<dim3(TSEQ / BLKQ, 4 * NHEAD), 256, ATTN_SMEM_BYTES>>>(
        pq, pk, pv, patt);
    // 4) proj + bias + residual(x) -> fp32 x1
    hgemm_kernel<1><<<dim3(CDIM / 128, BT / 128), 256, HGEMM_SMEM>>>(
        patt, pwprojT, BT, CDIM, CDIM, b_proj, x, px1, nullptr, nullptr, nullptr);
    // 5) ln2 -> fp16
    ln_kernel<<<BT, 256>>>(px1, g2, be2, ph2);
    // 6) ffn1: relu(h2 @ w1 + b1) -> fp16 ff
    hgemm_kernel<2><<<dim3(FFDIM / 128, BT / 128), 256, HGEMM_SMEM>>>(
        ph2, pw1T, BT, FFDIM, CDIM, b1, nullptr, nullptr, pff, nullptr, nullptr);
    // 7) ffn2: ff @ w2 + b2 + x1 -> fp32 out
    hgemm_kernel<3><<<dim3(CDIM / 128, BT / 128), 256, HGEMM_SMEM>>>(
        pff, pw2T, BT, CDIM, FFDIM, b2, px1, out, nullptr, nullptr, nullptr);
}